// round 1
// baseline (speedup 1.0000x reference)
#include <cuda_runtime.h>
#include <math.h>

#define N_TOK   8192
#define D_INP   768
#define D_OUT   64
#define NSPLIT  4
#define KEYS_PER_SPLIT (N_TOK / NSPLIT)   // 2048
#define BM      128
#define BN      64
#define PKB     32

// ---------------- scratch (device globals; no runtime allocation) ----------
__device__ float g_wq[N_TOK * D_OUT];                 // x @ Wk  (reference naming)
__device__ float g_wk[N_TOK * D_OUT];                 // x @ Wq
__device__ float g_wv[N_TOK * D_OUT];                 // x @ Wv
__device__ float g_opart[NSPLIT * N_TOK * D_OUT];     // unnormalized partial outputs
__device__ float g_m[NSPLIT * N_TOK];                 // per-split row max (scaled logits)
__device__ float g_l[NSPLIT * N_TOK];                 // per-split row sum-exp

// ---------------- projection: O[8192,64] = X[8192,768] @ W[768,64] ---------
// grid = (64 row-blocks, 3 weights), block = 256 (16x16), per-thread 8x4 tile
__global__ __launch_bounds__(256, 4)
void proj_kernel(const float* __restrict__ x,
                 const float* __restrict__ w_q,   // Wk in input order (ref swap)
                 const float* __restrict__ w_k,   // Wq
                 const float* __restrict__ w_v) {
    __shared__ float Xs[PKB * 132];   // transposed [k][row], pad 132
    __shared__ float Ws[PKB * 64];    // natural    [k][col]

    const float* W;
    float* O;
    if      (blockIdx.y == 0) { W = w_q; O = g_wq; }
    else if (blockIdx.y == 1) { W = w_k; O = g_wk; }
    else                      { W = w_v; O = g_wv; }

    const int tid = threadIdx.x;
    const int tx  = tid & 15;          // output col group (4 cols)
    const int ty  = tid >> 4;          // output row group (8 rows)
    const int row0 = blockIdx.x * BM;

    float acc[8][4];
#pragma unroll
    for (int i = 0; i < 8; i++)
#pragma unroll
        for (int j = 0; j < 4; j++) acc[i][j] = 0.0f;

    for (int kc = 0; kc < D_INP; kc += PKB) {
        // X tile 128x32 -> transposed smem
#pragma unroll
        for (int it = 0; it < 4; it++) {
            int idx = tid + it * 256;       // 0..1023
            int r   = idx >> 3;             // 0..127
            int c4  = idx & 7;              // 0..7
            float4 v = *(const float4*)&x[(size_t)(row0 + r) * D_INP + kc + c4 * 4];
            Xs[(c4 * 4 + 0) * 132 + r] = v.x;
            Xs[(c4 * 4 + 1) * 132 + r] = v.y;
            Xs[(c4 * 4 + 2) * 132 + r] = v.z;
            Xs[(c4 * 4 + 3) * 132 + r] = v.w;
        }
        // W tile 32x64 -> natural smem
#pragma unroll
        for (int it = 0; it < 2; it++) {
            int idx = tid + it * 256;       // 0..511
            int r   = idx >> 4;             // 0..31
            int c4  = idx & 15;             // 0..15
            *(float4*)&Ws[r * 64 + c4 * 4] =
                *(const float4*)&W[(size_t)(kc + r) * D_OUT + c4 * 4];
        }
        __syncthreads();

#pragma unroll 8
        for (int k = 0; k < PKB; k++) {
            float4 a0 = *(const float4*)&Xs[k * 132 + ty * 8];
            float4 a1 = *(const float4*)&Xs[k * 132 + ty * 8 + 4];
            float4 b  = *(const float4*)&Ws[k * 64 + tx * 4];
            float af[8] = {a0.x, a0.y, a0.z, a0.w, a1.x, a1.y, a1.z, a1.w};
            float bf[4] = {b.x, b.y, b.z, b.w};
#pragma unroll
            for (int i = 0; i < 8; i++)
#pragma unroll
                for (int j = 0; j < 4; j++)
                    acc[i][j] = fmaf(af[i], bf[j], acc[i][j]);
        }
        __syncthreads();
    }

#pragma unroll
    for (int i = 0; i < 8; i++) {
        float4 v = make_float4(acc[i][0], acc[i][1], acc[i][2], acc[i][3]);
        *(float4*)&O[(size_t)(row0 + ty * 8 + i) * D_OUT + tx * 4] = v;
    }
}

// ---------------- flash attention over a KV split --------------------------
// grid = (NSPLIT, 64 q-blocks), block = 256 (16x16)
// smem: Qs[64][132] | Ks[64][68] | Vs[64][64] | Ps[64][132]
#define QS_OFF 0
#define KS_OFF (64 * 132)
#define VS_OFF (KS_OFF + 64 * 68)
#define PS_OFF (VS_OFF + 64 * 64)
#define ATTN_SMEM_FLOATS (PS_OFF + 64 * 132)

extern __shared__ float smem[];

__global__ __launch_bounds__(256, 2)
void attn_kernel() {
    float* Qs = smem + QS_OFF;   // [k=64][row=128] stride 132
    float* Ks = smem + KS_OFF;   // [k=64][key=64]  stride 68
    float* Vs = smem + VS_OFF;   // [key=64][c=64]  stride 64
    float* Ps = smem + PS_OFF;   // [key=64][row=128] stride 132

    const int tid = threadIdx.x;
    const int tx  = tid & 15;    // key-col group (4) / out-col group (4)
    const int ty  = tid >> 4;    // q-row group (8)
    const int split = blockIdx.x;
    const int q0    = blockIdx.y * BM;
    const int k0base = split * KEYS_PER_SPLIT;

    // Load Q block once (transposed)
#pragma unroll
    for (int it = 0; it < 8; it++) {
        int idx = tid + it * 256;       // 0..2047
        int r   = idx >> 4;             // 0..127
        int c4  = idx & 15;             // 0..15
        float4 v = *(const float4*)&g_wq[(size_t)(q0 + r) * D_OUT + c4 * 4];
        Qs[(c4 * 4 + 0) * 132 + r] = v.x;
        Qs[(c4 * 4 + 1) * 132 + r] = v.y;
        Qs[(c4 * 4 + 2) * 132 + r] = v.z;
        Qs[(c4 * 4 + 3) * 132 + r] = v.w;
    }

    float o[8][4];
    float m[8], l[8];
#pragma unroll
    for (int i = 0; i < 8; i++) {
        m[i] = -1e30f; l[i] = 0.0f;
#pragma unroll
        for (int c = 0; c < 4; c++) o[i][c] = 0.0f;
    }

    const float cscale = 0.125f;   // 1/sqrt(64)

    for (int t = 0; t < KEYS_PER_SPLIT / BN; t++) {   // 32 tiles
        const int k0 = k0base + t * BN;
        __syncthreads();   // previous PV readers done before overwriting K/V

        // K tile (transposed) and V tile (natural)
#pragma unroll
        for (int it = 0; it < 4; it++) {
            int idx = tid + it * 256;   // 0..1023
            int key = idx >> 4;         // 0..63
            int c4  = idx & 15;
            float4 v = *(const float4*)&g_wk[(size_t)(k0 + key) * D_OUT + c4 * 4];
            Ks[(c4 * 4 + 0) * 68 + key] = v.x;
            Ks[(c4 * 4 + 1) * 68 + key] = v.y;
            Ks[(c4 * 4 + 2) * 68 + key] = v.z;
            Ks[(c4 * 4 + 3) * 68 + key] = v.w;
        }
#pragma unroll
        for (int it = 0; it < 4; it++) {
            int idx = tid + it * 256;
            int key = idx >> 4;
            int c4  = idx & 15;
            *(float4*)&Vs[key * 64 + c4 * 4] =
                *(const float4*)&g_wv[(size_t)(k0 + key) * D_OUT + c4 * 4];
        }
        __syncthreads();

        // S = Q Kᵀ  (8x4 per thread)
        float s[8][4];
#pragma unroll
        for (int i = 0; i < 8; i++)
#pragma unroll
            for (int j = 0; j < 4; j++) s[i][j] = 0.0f;

#pragma unroll 16
        for (int k = 0; k < D_OUT; k++) {
            float4 a0 = *(const float4*)&Qs[k * 132 + ty * 8];
            float4 a1 = *(const float4*)&Qs[k * 132 + ty * 8 + 4];
            float4 b  = *(const float4*)&Ks[k * 68 + tx * 4];
            float af[8] = {a0.x, a0.y, a0.z, a0.w, a1.x, a1.y, a1.z, a1.w};
            float bf[4] = {b.x, b.y, b.z, b.w};
#pragma unroll
            for (int i = 0; i < 8; i++)
#pragma unroll
                for (int j = 0; j < 4; j++)
                    s[i][j] = fmaf(af[i], bf[j], s[i][j]);
        }

        // online softmax (exact)
#pragma unroll
        for (int i = 0; i < 8; i++) {
            float rmax = -1e30f;
#pragma unroll
            for (int j = 0; j < 4; j++) {
                s[i][j] *= cscale;
                rmax = fmaxf(rmax, s[i][j]);
            }
#pragma unroll
            for (int off = 8; off >= 1; off >>= 1)
                rmax = fmaxf(rmax, __shfl_xor_sync(0xffffffffu, rmax, off));
            float mn = fmaxf(m[i], rmax);
            float alpha = __expf(m[i] - mn);
            m[i] = mn;
            float rs = 0.0f;
#pragma unroll
            for (int j = 0; j < 4; j++) {
                s[i][j] = __expf(s[i][j] - mn);
                rs += s[i][j];
            }
#pragma unroll
            for (int off = 8; off >= 1; off >>= 1)
                rs += __shfl_xor_sync(0xffffffffu, rs, off);
            l[i] = l[i] * alpha + rs;
#pragma unroll
            for (int c = 0; c < 4; c++) o[i][c] *= alpha;
        }

        // P -> smem transposed [key][row]
#pragma unroll
        for (int j = 0; j < 4; j++) {
            int key = tx * 4 + j;
            float4 t0 = make_float4(s[0][j], s[1][j], s[2][j], s[3][j]);
            float4 t1 = make_float4(s[4][j], s[5][j], s[6][j], s[7][j]);
            *(float4*)&Ps[key * 132 + ty * 8]     = t0;
            *(float4*)&Ps[key * 132 + ty * 8 + 4] = t1;
        }
        __syncthreads();

        // O += P V
#pragma unroll 16
        for (int j = 0; j < BN; j++) {
            float4 p0 = *(const float4*)&Ps[j * 132 + ty * 8];
            float4 p1 = *(const float4*)&Ps[j * 132 + ty * 8 + 4];
            float4 v4 = *(const float4*)&Vs[j * 64 + tx * 4];
            float pf[8] = {p0.x, p0.y, p0.z, p0.w, p1.x, p1.y, p1.z, p1.w};
            float vf[4] = {v4.x, v4.y, v4.z, v4.w};
#pragma unroll
            for (int i = 0; i < 8; i++)
#pragma unroll
                for (int c = 0; c < 4; c++)
                    o[i][c] = fmaf(pf[i], vf[c], o[i][c]);
        }
    }

    // epilogue: unnormalized partials + (m, l)
#pragma unroll
    for (int i = 0; i < 8; i++) {
        int r = split * N_TOK + q0 + ty * 8 + i;
        float4 v = make_float4(o[i][0], o[i][1], o[i][2], o[i][3]);
        *(float4*)&g_opart[(size_t)r * D_OUT + tx * 4] = v;
        if (tx == 0) { g_m[r] = m[i]; g_l[r] = l[i]; }
    }
}

// ---------------- merge the NSPLIT partials --------------------------------
__global__ __launch_bounds__(256)
void merge_kernel(float* __restrict__ out) {
    int idx = blockIdx.x * blockDim.x + threadIdx.x;  // over N_TOK * 16
    int row = idx >> 4;
    int c4  = (idx & 15) * 4;

    float M = -1e30f;
#pragma unroll
    for (int s = 0; s < NSPLIT; s++) M = fmaxf(M, g_m[s * N_TOK + row]);

    float L = 0.0f, w[NSPLIT];
#pragma unroll
    for (int s = 0; s < NSPLIT; s++) {
        w[s] = __expf(g_m[s * N_TOK + row] - M);
        L += g_l[s * N_TOK + row] * w[s];
    }
    float4 acc = make_float4(0.f, 0.f, 0.f, 0.f);
#pragma unroll
    for (int s = 0; s < NSPLIT; s++) {
        float4 v = *(const float4*)&g_opart[(size_t)(s * N_TOK + row) * D_OUT + c4];
        acc.x = fmaf(v.x, w[s], acc.x);
        acc.y = fmaf(v.y, w[s], acc.y);
        acc.z = fmaf(v.z, w[s], acc.z);
        acc.w = fmaf(v.w, w[s], acc.w);
    }
    float inv = 1.0f / L;
    acc.x *= inv; acc.y *= inv; acc.z *= inv; acc.w *= inv;
    *(float4*)&out[(size_t)row * D_OUT + c4] = acc;
}

// ---------------- launch ----------------------------------------------------
extern "C" void kernel_launch(void* const* d_in, const int* in_sizes, int n_in,
                              void* d_out, int out_size) {
    const float* x  = (const float*)d_in[0];
    const float* Wk = (const float*)d_in[1];   // used for the Q-side (reference swap)
    const float* Wq = (const float*)d_in[2];   // used for the K-side
    const float* Wv = (const float*)d_in[3];
    float* out = (float*)d_out;

    const int attn_smem = ATTN_SMEM_FLOATS * (int)sizeof(float);  // ~101 KB
    cudaFuncSetAttribute(attn_kernel,
                         cudaFuncAttributeMaxDynamicSharedMemorySize, attn_smem);

    proj_kernel<<<dim3(64, 3), 256>>>(x, Wk, Wq, Wv);
    attn_kernel<<<dim3(NSPLIT, 64), 256, attn_smem>>>();
    merge_kernel<<<(N_TOK * 16) / 256, 256>>>(out);
}

// round 3
// speedup vs baseline: 2.1248x; 2.1248x over previous
#include <cuda_runtime.h>
#include <cuda_bf16.h>
#include <cstdint>
#include <math.h>

#define N_TOK   8192
#define D_INP   768
#define D_OUT   64
#define NSPLIT  2
#define KPS     (N_TOK / NSPLIT)    // 4096 keys per split
#define BN      64                  // keys per tile
#define NT      (KPS / BN)          // 64 tiles

// ---------------- scratch (device globals) --------------------------------
__device__ __align__(16) uint32_t g_qhi[N_TOK * 32];   // bf16x2 pairs, [tok][32]
__device__ __align__(16) uint32_t g_qlo[N_TOK * 32];
__device__ __align__(16) uint32_t g_khi[N_TOK * 32];
__device__ __align__(16) uint32_t g_klo[N_TOK * 32];
__device__ __align__(16) float    g_wv [N_TOK * D_OUT];
__device__ __align__(16) uint16_t g_vThi[D_OUT * N_TOK];  // [dim][tok]
__device__ __align__(16) uint16_t g_vTlo[D_OUT * N_TOK];
__device__ float g_opart[NSPLIT * N_TOK * D_OUT];
__device__ float g_m[NSPLIT * N_TOK];
__device__ float g_l[NSPLIT * N_TOK];

// ---------------- helpers --------------------------------------------------
__device__ __forceinline__ void cvt_pair(float x, float y,
                                         uint32_t& hi, uint32_t& lo) {
    __nv_bfloat162 H = __floats2bfloat162_rn(x, y);          // .x = low half
    float rx = x - __bfloat162float(H.x);
    float ry = y - __bfloat162float(H.y);
    __nv_bfloat162 L = __floats2bfloat162_rn(rx, ry);
    hi = *reinterpret_cast<uint32_t*>(&H);
    lo = *reinterpret_cast<uint32_t*>(&L);
}

// mma.sync m16n8k16 bf16 (row.col), f32 accumulate in place
__device__ __forceinline__ void mma16816(float* d, const uint32_t* a,
                                         uint32_t b0, uint32_t b1) {
    asm volatile(
        "mma.sync.aligned.m16n8k16.row.col.f32.bf16.bf16.f32 "
        "{%0,%1,%2,%3}, {%4,%5,%6,%7}, {%8,%9}, {%0,%1,%2,%3};\n"
        : "+f"(d[0]), "+f"(d[1]), "+f"(d[2]), "+f"(d[3])
        : "r"(a[0]), "r"(a[1]), "r"(a[2]), "r"(a[3]), "r"(b0), "r"(b1));
}

// ---------------- projection: O = X @ W, + bf16 split epilogue -------------
__global__ __launch_bounds__(256)
void proj_kernel(const float* __restrict__ x,
                 const float* __restrict__ w_q,   // d_in[1] (reference swap)
                 const float* __restrict__ w_k,   // d_in[2]
                 const float* __restrict__ w_v) {
    __shared__ float Xs[32 * 68];
    __shared__ float Ws[32 * 64];

    const float* W;
    if      (blockIdx.y == 0) W = w_q;
    else if (blockIdx.y == 1) W = w_k;
    else                      W = w_v;

    const int tid = threadIdx.x;
    const int tx = tid & 15, ty = tid >> 4;
    const int row0 = blockIdx.x * 64;

    float acc[4][4];
#pragma unroll
    for (int i = 0; i < 4; i++)
#pragma unroll
        for (int j = 0; j < 4; j++) acc[i][j] = 0.0f;

    for (int kc = 0; kc < D_INP; kc += 32) {
#pragma unroll
        for (int it = 0; it < 2; it++) {
            int idx = tid + it * 256;
            int r = idx >> 3, c4 = idx & 7;
            float4 v = *(const float4*)&x[(size_t)(row0 + r) * D_INP + kc + c4 * 4];
            Xs[(c4 * 4 + 0) * 68 + r] = v.x;
            Xs[(c4 * 4 + 1) * 68 + r] = v.y;
            Xs[(c4 * 4 + 2) * 68 + r] = v.z;
            Xs[(c4 * 4 + 3) * 68 + r] = v.w;
        }
#pragma unroll
        for (int it = 0; it < 2; it++) {
            int idx = tid + it * 256;
            int r = idx >> 4, c4 = idx & 15;
            *(float4*)&Ws[r * 64 + c4 * 4] =
                *(const float4*)&W[(size_t)(kc + r) * D_OUT + c4 * 4];
        }
        __syncthreads();
#pragma unroll
        for (int k = 0; k < 32; k++) {
            float4 a = *(const float4*)&Xs[k * 68 + ty * 4];
            float4 b = *(const float4*)&Ws[k * 64 + tx * 4];
            float af[4] = {a.x, a.y, a.z, a.w};
            float bf[4] = {b.x, b.y, b.z, b.w};
#pragma unroll
            for (int i = 0; i < 4; i++)
#pragma unroll
                for (int j = 0; j < 4; j++)
                    acc[i][j] = fmaf(af[i], bf[j], acc[i][j]);
        }
        __syncthreads();
    }

    if (blockIdx.y < 2) {
        uint32_t* HI = (blockIdx.y == 0) ? g_qhi : g_khi;
        uint32_t* LO = (blockIdx.y == 0) ? g_qlo : g_klo;
        const float sc = (blockIdx.y == 0) ? 0.125f : 1.0f;   // fold 1/sqrt(64) into Q
#pragma unroll
        for (int i = 0; i < 4; i++) {
            int row = row0 + ty * 4 + i;
            uint32_t h0, l0, h1, l1;
            cvt_pair(acc[i][0] * sc, acc[i][1] * sc, h0, l0);
            cvt_pair(acc[i][2] * sc, acc[i][3] * sc, h1, l1);
            HI[row * 32 + tx * 2]     = h0;
            HI[row * 32 + tx * 2 + 1] = h1;
            LO[row * 32 + tx * 2]     = l0;
            LO[row * 32 + tx * 2 + 1] = l1;
        }
    } else {
#pragma unroll
        for (int i = 0; i < 4; i++) {
            float4 v = make_float4(acc[i][0], acc[i][1], acc[i][2], acc[i][3]);
            *(float4*)&g_wv[(size_t)(row0 + ty * 4 + i) * D_OUT + tx * 4] = v;
        }
    }
}

// ---------------- V transpose + bf16 split ---------------------------------
__global__ __launch_bounds__(256)
void transpose_v_kernel() {
    __shared__ float tile[32][33];
    int r0 = blockIdx.x * 32;   // token
    int c0 = blockIdx.y * 32;   // dim
    int tx = threadIdx.x & 31, ty = threadIdx.x >> 5;
#pragma unroll
    for (int i = 0; i < 4; i++)
        tile[ty + i * 8][tx] = g_wv[(size_t)(r0 + ty + i * 8) * D_OUT + c0 + tx];
    __syncthreads();
#pragma unroll
    for (int i = 0; i < 4; i++) {
        float v = tile[tx][ty + i * 8];
        __nv_bfloat16 h = __float2bfloat16_rn(v);
        float rr = v - __bfloat162float(h);
        __nv_bfloat16 lo = __float2bfloat16_rn(rr);
        int dim = c0 + ty + i * 8, tok = r0 + tx;
        g_vThi[(size_t)dim * N_TOK + tok] = *reinterpret_cast<uint16_t*>(&h);
        g_vTlo[(size_t)dim * N_TOK + tok] = *reinterpret_cast<uint16_t*>(&lo);
    }
}

// ---------------- flash attention: mma.sync split-bf16 ---------------------
// grid (NSPLIT, 64), block 256 (8 warps). Warp w owns q rows q0+16w..+15.
// smem: double-buffered tiles, 144 B row stride (conflict-free frag loads).
#define TILE_B 9216                  // 64 rows * 144 B
#define OFF_KHI 0
#define OFF_KLO TILE_B
#define OFF_VHI (2 * TILE_B)
#define OFF_VLO (3 * TILE_B)
#define BUF_B   (4 * TILE_B)         // 36864
#define SMEM_TOTAL (2 * BUF_B)       // 73728

extern __shared__ char dsm[];

__device__ __forceinline__ void copy_tile(char* dst, int k0, int tid) {
#pragma unroll
    for (int it = 0; it < 2; it++) {
        int id = it * 256 + tid;          // 0..511
        int row = id >> 3, cc = id & 7;   // row 0..63, 8 uint4 per 128B row
        int doff = row * 144 + cc * 16;
        // K hi/lo: rows = keys
        *(uint4*)(dst + OFF_KHI + doff) =
            ((const uint4*)g_khi)[(size_t)(k0 + row) * 8 + cc];
        *(uint4*)(dst + OFF_KLO + doff) =
            ((const uint4*)g_klo)[(size_t)(k0 + row) * 8 + cc];
        // V hi/lo: rows = dims, cols = keys k0..k0+63
        *(uint4*)(dst + OFF_VHI + doff) =
            ((const uint4*)g_vThi)[(size_t)row * (N_TOK / 8) + k0 / 8 + cc];
        *(uint4*)(dst + OFF_VLO + doff) =
            ((const uint4*)g_vTlo)[(size_t)row * (N_TOK / 8) + k0 / 8 + cc];
    }
}

__global__ __launch_bounds__(256, 1)
void attn_kernel() {
    const int tid = threadIdx.x;
    const int w = tid >> 5, lane = tid & 31;
    const int r = lane >> 2, c = lane & 3;
    const int split = blockIdx.x;
    const int q0 = blockIdx.y * 128;
    const int row0 = q0 + w * 16 + r;    // this thread's first q row
    const int row8 = row0 + 8;

    // ---- Q fragments (hi/lo), resident for the whole kernel ----
    uint32_t qh[4][4], ql[4][4];
#pragma unroll
    for (int kb = 0; kb < 4; kb++) {
        int base = kb * 8 + c;
        qh[kb][0] = g_qhi[row0 * 32 + base];
        qh[kb][1] = g_qhi[row8 * 32 + base];
        qh[kb][2] = g_qhi[row0 * 32 + base + 4];
        qh[kb][3] = g_qhi[row8 * 32 + base + 4];
        ql[kb][0] = g_qlo[row0 * 32 + base];
        ql[kb][1] = g_qlo[row8 * 32 + base];
        ql[kb][2] = g_qlo[row0 * 32 + base + 4];
        ql[kb][3] = g_qlo[row8 * 32 + base + 4];
    }

    float o[8][4];
#pragma unroll
    for (int nb = 0; nb < 8; nb++)
#pragma unroll
        for (int j = 0; j < 4; j++) o[nb][j] = 0.0f;
    float m0 = -1e30f, m1 = -1e30f, l0 = 0.0f, l1 = 0.0f;

    const int kbase = split * KPS;
    copy_tile(dsm, kbase, tid);

    for (int t = 0; t < NT; t++) {
        __syncthreads();
        if (t + 1 < NT)
            copy_tile(dsm + ((t + 1) & 1) * BUF_B, kbase + (t + 1) * BN, tid);
        char* buf = dsm + (t & 1) * BUF_B;

        // ---- S = Q Kᵀ (3-term split) ----
        float s[8][4];
#pragma unroll
        for (int nb = 0; nb < 8; nb++)
#pragma unroll
            for (int j = 0; j < 4; j++) s[nb][j] = 0.0f;

#pragma unroll
        for (int kb = 0; kb < 4; kb++) {
#pragma unroll
            for (int nb = 0; nb < 8; nb++) {
                int key = nb * 8 + r;
                const char* kp = buf + OFF_KHI + key * 144 + kb * 32 + c * 4;
                uint32_t bh0 = *(const uint32_t*)kp;
                uint32_t bh1 = *(const uint32_t*)(kp + 16);
                uint32_t bl0 = *(const uint32_t*)(kp + TILE_B);
                uint32_t bl1 = *(const uint32_t*)(kp + TILE_B + 16);
                mma16816(s[nb], qh[kb], bh0, bh1);
                mma16816(s[nb], qh[kb], bl0, bl1);
                mma16816(s[nb], ql[kb], bh0, bh1);
            }
        }

        // ---- online softmax (rows r and r+8, reduce over quad) ----
        float mx0 = -1e30f, mx1 = -1e30f;
#pragma unroll
        for (int nb = 0; nb < 8; nb++) {
            mx0 = fmaxf(mx0, fmaxf(s[nb][0], s[nb][1]));
            mx1 = fmaxf(mx1, fmaxf(s[nb][2], s[nb][3]));
        }
        mx0 = fmaxf(mx0, __shfl_xor_sync(0xffffffffu, mx0, 1));
        mx0 = fmaxf(mx0, __shfl_xor_sync(0xffffffffu, mx0, 2));
        mx1 = fmaxf(mx1, __shfl_xor_sync(0xffffffffu, mx1, 1));
        mx1 = fmaxf(mx1, __shfl_xor_sync(0xffffffffu, mx1, 2));

        float nm0 = fmaxf(m0, mx0), nm1 = fmaxf(m1, mx1);
        float a0 = __expf(m0 - nm0), a1 = __expf(m1 - nm1);
        m0 = nm0; m1 = nm1;

        float rs0 = 0.0f, rs1 = 0.0f;
#pragma unroll
        for (int nb = 0; nb < 8; nb++) {
            s[nb][0] = __expf(s[nb][0] - nm0);
            s[nb][1] = __expf(s[nb][1] - nm0);
            s[nb][2] = __expf(s[nb][2] - nm1);
            s[nb][3] = __expf(s[nb][3] - nm1);
            rs0 += s[nb][0] + s[nb][1];
            rs1 += s[nb][2] + s[nb][3];
        }
        rs0 += __shfl_xor_sync(0xffffffffu, rs0, 1);
        rs0 += __shfl_xor_sync(0xffffffffu, rs0, 2);
        rs1 += __shfl_xor_sync(0xffffffffu, rs1, 1);
        rs1 += __shfl_xor_sync(0xffffffffu, rs1, 2);
        l0 = l0 * a0 + rs0;
        l1 = l1 * a1 + rs1;

#pragma unroll
        for (int nb = 0; nb < 8; nb++) {
            o[nb][0] *= a0; o[nb][1] *= a0;
            o[nb][2] *= a1; o[nb][3] *= a1;
        }

        // ---- O += P V (P built in registers from S fragments) ----
#pragma unroll
        for (int kb = 0; kb < 4; kb++) {
            uint32_t ah[4], al[4];
            cvt_pair(s[2 * kb][0],     s[2 * kb][1],     ah[0], al[0]);
            cvt_pair(s[2 * kb][2],     s[2 * kb][3],     ah[1], al[1]);
            cvt_pair(s[2 * kb + 1][0], s[2 * kb + 1][1], ah[2], al[2]);
            cvt_pair(s[2 * kb + 1][2], s[2 * kb + 1][3], ah[3], al[3]);
#pragma unroll
            for (int nb = 0; nb < 8; nb++) {
                int dim = nb * 8 + r;
                const char* vp = buf + OFF_VHI + dim * 144 + kb * 32 + c * 4;
                uint32_t bh0 = *(const uint32_t*)vp;
                uint32_t bh1 = *(const uint32_t*)(vp + 16);
                uint32_t bl0 = *(const uint32_t*)(vp + TILE_B);
                uint32_t bl1 = *(const uint32_t*)(vp + TILE_B + 16);
                mma16816(o[nb], ah, bh0, bh1);
                mma16816(o[nb], ah, bl0, bl1);
                mma16816(o[nb], al, bh0, bh1);
            }
        }
    }

    // ---- epilogue: unnormalized partials + (m, l) ----
    size_t orow0 = (size_t)split * N_TOK + q0 + w * 16 + r;
    size_t orow8 = orow0 + 8;
#pragma unroll
    for (int nb = 0; nb < 8; nb++) {
        int cc = nb * 8 + 2 * c;
        g_opart[orow0 * D_OUT + cc]     = o[nb][0];
        g_opart[orow0 * D_OUT + cc + 1] = o[nb][1];
        g_opart[orow8 * D_OUT + cc]     = o[nb][2];
        g_opart[orow8 * D_OUT + cc + 1] = o[nb][3];
    }
    if (c == 0) {
        g_m[orow0] = m0; g_l[orow0] = l0;
        g_m[orow8] = m1; g_l[orow8] = l1;
    }
}

// ---------------- merge -----------------------------------------------------
__global__ __launch_bounds__(256)
void merge_kernel(float* __restrict__ out) {
    int idx = blockIdx.x * blockDim.x + threadIdx.x;
    int row = idx >> 4;
    int c4 = (idx & 15) * 4;

    float M = -1e30f;
#pragma unroll
    for (int s = 0; s < NSPLIT; s++) M = fmaxf(M, g_m[s * N_TOK + row]);
    float L = 0.0f, w[NSPLIT];
#pragma unroll
    for (int s = 0; s < NSPLIT; s++) {
        w[s] = __expf(g_m[s * N_TOK + row] - M);
        L += g_l[s * N_TOK + row] * w[s];
    }
    float4 acc = make_float4(0.f, 0.f, 0.f, 0.f);
#pragma unroll
    for (int s = 0; s < NSPLIT; s++) {
        float4 v = *(const float4*)&g_opart[(size_t)(s * N_TOK + row) * D_OUT + c4];
        acc.x = fmaf(v.x, w[s], acc.x);
        acc.y = fmaf(v.y, w[s], acc.y);
        acc.z = fmaf(v.z, w[s], acc.z);
        acc.w = fmaf(v.w, w[s], acc.w);
    }
    float inv = 1.0f / L;
    acc.x *= inv; acc.y *= inv; acc.z *= inv; acc.w *= inv;
    *(float4*)&out[(size_t)row * D_OUT + c4] = acc;
}

// ---------------- launch -----------------------------------------------------
extern "C" void kernel_launch(void* const* d_in, const int* in_sizes, int n_in,
                              void* d_out, int out_size) {
    const float* x  = (const float*)d_in[0];
    const float* Wk = (const float*)d_in[1];   // Q side (reference swap)
    const float* Wq = (const float*)d_in[2];   // K side
    const float* Wv = (const float*)d_in[3];
    float* out = (float*)d_out;

    cudaFuncSetAttribute(attn_kernel,
                         cudaFuncAttributeMaxDynamicSharedMemorySize, SMEM_TOTAL);

    proj_kernel<<<dim3(128, 3), 256>>>(x, Wk, Wq, Wv);
    transpose_v_kernel<<<dim3(N_TOK / 32, D_OUT / 32), 256>>>();
    attn_kernel<<<dim3(NSPLIT, 64), 256, SMEM_TOTAL>>>();
    merge_kernel<<<(N_TOK * 16) / 256, 256>>>(out);
}

// round 4
// speedup vs baseline: 2.3408x; 1.1016x over previous
#include <cuda_runtime.h>
#include <cuda_bf16.h>
#include <cstdint>
#include <math.h>

#define N_TOK   8192
#define D_INP   768
#define D_OUT   64
#define NSPLIT  4
#define KPS     (N_TOK / NSPLIT)    // 2048 keys per split
#define BN      64                  // keys per tile
#define NT      (KPS / BN)          // 32 tiles

// ---------------- scratch (device globals) --------------------------------
__device__ __align__(16) uint32_t g_qhi[N_TOK * 32];   // bf16x2 pairs, [tok][32]
__device__ __align__(16) uint32_t g_qlo[N_TOK * 32];
__device__ __align__(16) uint32_t g_khi[N_TOK * 32];
__device__ __align__(16) uint32_t g_klo[N_TOK * 32];
__device__ __align__(16) float    g_wv [N_TOK * D_OUT];
__device__ __align__(16) uint16_t g_vThi[D_OUT * N_TOK];  // [dim][tok]
__device__ __align__(16) uint16_t g_vTlo[D_OUT * N_TOK];
__device__ float g_opart[NSPLIT * N_TOK * D_OUT];
__device__ float g_m[NSPLIT * N_TOK];   // log2-domain row max
__device__ float g_l[NSPLIT * N_TOK];

#define QSCALE 0.1803368801111372f     // (1/8) * log2(e)

// ---------------- helpers --------------------------------------------------
__device__ __forceinline__ void cvt_pair(float x, float y,
                                         uint32_t& hi, uint32_t& lo) {
    __nv_bfloat162 H = __floats2bfloat162_rn(x, y);
    float rx = x - __bfloat162float(H.x);
    float ry = y - __bfloat162float(H.y);
    __nv_bfloat162 L = __floats2bfloat162_rn(rx, ry);
    hi = *reinterpret_cast<uint32_t*>(&H);
    lo = *reinterpret_cast<uint32_t*>(&L);
}

__device__ __forceinline__ void mma16816(float* d, const uint32_t* a,
                                         uint32_t b0, uint32_t b1) {
    asm volatile(
        "mma.sync.aligned.m16n8k16.row.col.f32.bf16.bf16.f32 "
        "{%0,%1,%2,%3}, {%4,%5,%6,%7}, {%8,%9}, {%0,%1,%2,%3};\n"
        : "+f"(d[0]), "+f"(d[1]), "+f"(d[2]), "+f"(d[3])
        : "r"(a[0]), "r"(a[1]), "r"(a[2]), "r"(a[3]), "r"(b0), "r"(b1));
}

__device__ __forceinline__ uint32_t smem_u32(const void* p) {
    uint32_t a;
    asm("{ .reg .u64 t; cvta.to.shared.u64 t, %1; cvt.u32.u64 %0, t; }"
        : "=r"(a) : "l"(p));
    return a;
}

#define CP_ASYNC16(d, s) \
    asm volatile("cp.async.cg.shared.global [%0], [%1], 16;" \
                 :: "r"(d), "l"(s) : "memory")
#define CP_COMMIT() asm volatile("cp.async.commit_group;" ::: "memory")
#define CP_WAIT1()  asm volatile("cp.async.wait_group 1;" ::: "memory")
#define CP_WAIT0()  asm volatile("cp.async.wait_group 0;" ::: "memory")

// ---------------- projection: O = X @ W, + bf16 split epilogue -------------
__global__ __launch_bounds__(256)
void proj_kernel(const float* __restrict__ x,
                 const float* __restrict__ w_q,
                 const float* __restrict__ w_k,
                 const float* __restrict__ w_v) {
    __shared__ float Xs[32 * 68];
    __shared__ float Ws[32 * 64];

    const float* W;
    if      (blockIdx.y == 0) W = w_q;
    else if (blockIdx.y == 1) W = w_k;
    else                      W = w_v;

    const int tid = threadIdx.x;
    const int tx = tid & 15, ty = tid >> 4;
    const int row0 = blockIdx.x * 64;

    float acc[4][4];
#pragma unroll
    for (int i = 0; i < 4; i++)
#pragma unroll
        for (int j = 0; j < 4; j++) acc[i][j] = 0.0f;

    for (int kc = 0; kc < D_INP; kc += 32) {
#pragma unroll
        for (int it = 0; it < 2; it++) {
            int idx = tid + it * 256;
            int r = idx >> 3, c4 = idx & 7;
            float4 v = *(const float4*)&x[(size_t)(row0 + r) * D_INP + kc + c4 * 4];
            Xs[(c4 * 4 + 0) * 68 + r] = v.x;
            Xs[(c4 * 4 + 1) * 68 + r] = v.y;
            Xs[(c4 * 4 + 2) * 68 + r] = v.z;
            Xs[(c4 * 4 + 3) * 68 + r] = v.w;
        }
#pragma unroll
        for (int it = 0; it < 2; it++) {
            int idx = tid + it * 256;
            int r = idx >> 4, c4 = idx & 15;
            *(float4*)&Ws[r * 64 + c4 * 4] =
                *(const float4*)&W[(size_t)(kc + r) * D_OUT + c4 * 4];
        }
        __syncthreads();
#pragma unroll
        for (int k = 0; k < 32; k++) {
            float4 a = *(const float4*)&Xs[k * 68 + ty * 4];
            float4 b = *(const float4*)&Ws[k * 64 + tx * 4];
            float af[4] = {a.x, a.y, a.z, a.w};
            float bf[4] = {b.x, b.y, b.z, b.w};
#pragma unroll
            for (int i = 0; i < 4; i++)
#pragma unroll
                for (int j = 0; j < 4; j++)
                    acc[i][j] = fmaf(af[i], bf[j], acc[i][j]);
        }
        __syncthreads();
    }

    if (blockIdx.y < 2) {
        uint32_t* HI = (blockIdx.y == 0) ? g_qhi : g_khi;
        uint32_t* LO = (blockIdx.y == 0) ? g_qlo : g_klo;
        const float sc = (blockIdx.y == 0) ? QSCALE : 1.0f;
#pragma unroll
        for (int i = 0; i < 4; i++) {
            int row = row0 + ty * 4 + i;
            uint32_t h0, l0, h1, l1;
            cvt_pair(acc[i][0] * sc, acc[i][1] * sc, h0, l0);
            cvt_pair(acc[i][2] * sc, acc[i][3] * sc, h1, l1);
            HI[row * 32 + tx * 2]     = h0;
            HI[row * 32 + tx * 2 + 1] = h1;
            LO[row * 32 + tx * 2]     = l0;
            LO[row * 32 + tx * 2 + 1] = l1;
        }
    } else {
#pragma unroll
        for (int i = 0; i < 4; i++) {
            float4 v = make_float4(acc[i][0], acc[i][1], acc[i][2], acc[i][3]);
            *(float4*)&g_wv[(size_t)(row0 + ty * 4 + i) * D_OUT + tx * 4] = v;
        }
    }
}

// ---------------- V transpose + bf16 split ---------------------------------
__global__ __launch_bounds__(256)
void transpose_v_kernel() {
    __shared__ float tile[32][33];
    int r0 = blockIdx.x * 32;   // token
    int c0 = blockIdx.y * 32;   // dim
    int tx = threadIdx.x & 31, ty = threadIdx.x >> 5;
#pragma unroll
    for (int i = 0; i < 4; i++)
        tile[ty + i * 8][tx] = g_wv[(size_t)(r0 + ty + i * 8) * D_OUT + c0 + tx];
    __syncthreads();
#pragma unroll
    for (int i = 0; i < 4; i++) {
        float v = tile[tx][ty + i * 8];
        __nv_bfloat16 h = __float2bfloat16_rn(v);
        float rr = v - __bfloat162float(h);
        __nv_bfloat16 lo = __float2bfloat16_rn(rr);
        int dim = c0 + ty + i * 8, tok = r0 + tx;
        g_vThi[(size_t)dim * N_TOK + tok] = *reinterpret_cast<uint16_t*>(&h);
        g_vTlo[(size_t)dim * N_TOK + tok] = *reinterpret_cast<uint16_t*>(&lo);
    }
}

// ---------------- flash attention -----------------------------------------
// grid (NSPLIT, 64), block 128 (4 warps). Warp w owns q rows q0+32w..+31
// (two m16 fragments). Double-buffered K/V tiles via cp.async.
#define TILE_B 9216                  // 64 rows * 144 B
#define OFF_KHI 0
#define OFF_KLO TILE_B
#define OFF_VHI (2 * TILE_B)
#define OFF_VLO (3 * TILE_B)
#define BUF_B   (4 * TILE_B)         // 36864
#define SMEM_TOTAL (2 * BUF_B)       // 73728

extern __shared__ char dsm[];

__device__ __forceinline__ void copy_tile_async(uint32_t sbuf, int k0, int tid) {
#pragma unroll
    for (int it = 0; it < 4; it++) {
        int id = it * 128 + tid;          // 0..511
        int row = id >> 3, cc = id & 7;   // row 0..63, chunk 0..7 (16B)
        uint32_t doff = row * 144 + cc * 16;
        CP_ASYNC16(sbuf + OFF_KHI + doff,
                   (const char*)g_khi + (size_t)(k0 + row) * 128 + cc * 16);
        CP_ASYNC16(sbuf + OFF_KLO + doff,
                   (const char*)g_klo + (size_t)(k0 + row) * 128 + cc * 16);
        CP_ASYNC16(sbuf + OFF_VHI + doff,
                   (const char*)g_vThi + (size_t)row * (N_TOK * 2) + (size_t)k0 * 2 + cc * 16);
        CP_ASYNC16(sbuf + OFF_VLO + doff,
                   (const char*)g_vTlo + (size_t)row * (N_TOK * 2) + (size_t)k0 * 2 + cc * 16);
    }
}

__global__ __launch_bounds__(128, 2)
void attn_kernel() {
    const int tid = threadIdx.x;
    const int w = tid >> 5, lane = tid & 31;
    const int r = lane >> 2, c = lane & 3;
    const int split = blockIdx.x;
    const int q0 = blockIdx.y * 128;
    const uint32_t sb = smem_u32(dsm);

    // ---- Q fragments (2 m-frags x hi/lo), resident all kernel ----
    uint32_t qh[2][4][4], ql[2][4][4];
#pragma unroll
    for (int mf = 0; mf < 2; mf++) {
        int ra = q0 + w * 32 + mf * 16 + r;
        int rb = ra + 8;
#pragma unroll
        for (int kb = 0; kb < 4; kb++) {
            int base = kb * 8 + c;
            qh[mf][kb][0] = g_qhi[ra * 32 + base];
            qh[mf][kb][1] = g_qhi[rb * 32 + base];
            qh[mf][kb][2] = g_qhi[ra * 32 + base + 4];
            qh[mf][kb][3] = g_qhi[rb * 32 + base + 4];
            ql[mf][kb][0] = g_qlo[ra * 32 + base];
            ql[mf][kb][1] = g_qlo[rb * 32 + base];
            ql[mf][kb][2] = g_qlo[ra * 32 + base + 4];
            ql[mf][kb][3] = g_qlo[rb * 32 + base + 4];
        }
    }

    float o[2][8][4];
#pragma unroll
    for (int mf = 0; mf < 2; mf++)
#pragma unroll
        for (int nb = 0; nb < 8; nb++)
#pragma unroll
            for (int j = 0; j < 4; j++) o[mf][nb][j] = 0.0f;
    float m[2][2] = {{-1e30f, -1e30f}, {-1e30f, -1e30f}};
    float l[2][2] = {{0.0f, 0.0f}, {0.0f, 0.0f}};

    const int kbase = split * KPS;
    copy_tile_async(sb, kbase, tid);
    CP_COMMIT();

    for (int t = 0; t < NT; t++) {
        if (t + 1 < NT) {
            copy_tile_async(sb + ((t + 1) & 1) * BUF_B, kbase + (t + 1) * BN, tid);
            CP_COMMIT();
            CP_WAIT1();
        } else {
            CP_WAIT0();
        }
        __syncthreads();                      // tile t visible to all warps
        const char* buf = dsm + (t & 1) * BUF_B;

        // ---- S = Q Kᵀ (3-term split), log2-domain logits ----
        float s[2][8][4];
#pragma unroll
        for (int mf = 0; mf < 2; mf++)
#pragma unroll
            for (int nb = 0; nb < 8; nb++)
#pragma unroll
                for (int j = 0; j < 4; j++) s[mf][nb][j] = 0.0f;

#pragma unroll
        for (int kb = 0; kb < 4; kb++) {
#pragma unroll
            for (int nb = 0; nb < 8; nb++) {
                int key = nb * 8 + r;
                const char* kp = buf + OFF_KHI + key * 144 + kb * 32 + c * 4;
                uint32_t bh0 = *(const uint32_t*)kp;
                uint32_t bh1 = *(const uint32_t*)(kp + 16);
                uint32_t bl0 = *(const uint32_t*)(kp + TILE_B);
                uint32_t bl1 = *(const uint32_t*)(kp + TILE_B + 16);
#pragma unroll
                for (int mf = 0; mf < 2; mf++) {
                    mma16816(s[mf][nb], qh[mf][kb], bh0, bh1);
                    mma16816(s[mf][nb], qh[mf][kb], bl0, bl1);
                    mma16816(s[mf][nb], ql[mf][kb], bh0, bh1);
                }
            }
        }

        // ---- online softmax in exp2 domain ----
        float alpha[2][2];
#pragma unroll
        for (int mf = 0; mf < 2; mf++) {
            float mx0 = -1e30f, mx1 = -1e30f;
#pragma unroll
            for (int nb = 0; nb < 8; nb++) {
                mx0 = fmaxf(mx0, fmaxf(s[mf][nb][0], s[mf][nb][1]));
                mx1 = fmaxf(mx1, fmaxf(s[mf][nb][2], s[mf][nb][3]));
            }
            mx0 = fmaxf(mx0, __shfl_xor_sync(0xffffffffu, mx0, 1));
            mx0 = fmaxf(mx0, __shfl_xor_sync(0xffffffffu, mx0, 2));
            mx1 = fmaxf(mx1, __shfl_xor_sync(0xffffffffu, mx1, 1));
            mx1 = fmaxf(mx1, __shfl_xor_sync(0xffffffffu, mx1, 2));

            float nm0 = fmaxf(m[mf][0], mx0), nm1 = fmaxf(m[mf][1], mx1);
            alpha[mf][0] = exp2f(m[mf][0] - nm0);
            alpha[mf][1] = exp2f(m[mf][1] - nm1);
            m[mf][0] = nm0; m[mf][1] = nm1;

            float rs0 = 0.0f, rs1 = 0.0f;
#pragma unroll
            for (int nb = 0; nb < 8; nb++) {
                s[mf][nb][0] = exp2f(s[mf][nb][0] - nm0);
                s[mf][nb][1] = exp2f(s[mf][nb][1] - nm0);
                s[mf][nb][2] = exp2f(s[mf][nb][2] - nm1);
                s[mf][nb][3] = exp2f(s[mf][nb][3] - nm1);
                rs0 += s[mf][nb][0] + s[mf][nb][1];
                rs1 += s[mf][nb][2] + s[mf][nb][3];
            }
            rs0 += __shfl_xor_sync(0xffffffffu, rs0, 1);
            rs0 += __shfl_xor_sync(0xffffffffu, rs0, 2);
            rs1 += __shfl_xor_sync(0xffffffffu, rs1, 1);
            rs1 += __shfl_xor_sync(0xffffffffu, rs1, 2);
            l[mf][0] = l[mf][0] * alpha[mf][0] + rs0;
            l[mf][1] = l[mf][1] * alpha[mf][1] + rs1;

#pragma unroll
            for (int nb = 0; nb < 8; nb++) {
                o[mf][nb][0] *= alpha[mf][0]; o[mf][nb][1] *= alpha[mf][0];
                o[mf][nb][2] *= alpha[mf][1]; o[mf][nb][3] *= alpha[mf][1];
            }
        }

        // ---- O += P V (P built in registers) ----
#pragma unroll
        for (int kb = 0; kb < 4; kb++) {
            uint32_t ah[2][4], al[2][4];
#pragma unroll
            for (int mf = 0; mf < 2; mf++) {
                cvt_pair(s[mf][2 * kb][0],     s[mf][2 * kb][1],     ah[mf][0], al[mf][0]);
                cvt_pair(s[mf][2 * kb][2],     s[mf][2 * kb][3],     ah[mf][1], al[mf][1]);
                cvt_pair(s[mf][2 * kb + 1][0], s[mf][2 * kb + 1][1], ah[mf][2], al[mf][2]);
                cvt_pair(s[mf][2 * kb + 1][2], s[mf][2 * kb + 1][3], ah[mf][3], al[mf][3]);
            }
#pragma unroll
            for (int nb = 0; nb < 8; nb++) {
                int dim = nb * 8 + r;
                const char* vp = buf + OFF_VHI + dim * 144 + kb * 32 + c * 4;
                uint32_t bh0 = *(const uint32_t*)vp;
                uint32_t bh1 = *(const uint32_t*)(vp + 16);
                uint32_t bl0 = *(const uint32_t*)(vp + TILE_B);
                uint32_t bl1 = *(const uint32_t*)(vp + TILE_B + 16);
#pragma unroll
                for (int mf = 0; mf < 2; mf++) {
                    mma16816(o[mf][nb], ah[mf], bh0, bh1);
                    mma16816(o[mf][nb], ah[mf], bl0, bl1);
                    mma16816(o[mf][nb], al[mf], bh0, bh1);
                }
            }
        }
        __syncthreads();                      // all warps done with buf t
    }

    // ---- epilogue ----
#pragma unroll
    for (int mf = 0; mf < 2; mf++) {
        size_t orow0 = (size_t)split * N_TOK + q0 + w * 32 + mf * 16 + r;
        size_t orow8 = orow0 + 8;
#pragma unroll
        for (int nb = 0; nb < 8; nb++) {
            int cc = nb * 8 + 2 * c;
            g_opart[orow0 * D_OUT + cc]     = o[mf][nb][0];
            g_opart[orow0 * D_OUT + cc + 1] = o[mf][nb][1];
            g_opart[orow8 * D_OUT + cc]     = o[mf][nb][2];
            g_opart[orow8 * D_OUT + cc + 1] = o[mf][nb][3];
        }
        if (c == 0) {
            g_m[orow0] = m[mf][0]; g_l[orow0] = l[mf][0];
            g_m[orow8] = m[mf][1]; g_l[orow8] = l[mf][1];
        }
    }
}

// ---------------- merge (log2-domain m) ------------------------------------
__global__ __launch_bounds__(256)
void merge_kernel(float* __restrict__ out) {
    int idx = blockIdx.x * blockDim.x + threadIdx.x;
    int row = idx >> 4;
    int c4 = (idx & 15) * 4;

    float M = -1e30f;
#pragma unroll
    for (int s = 0; s < NSPLIT; s++) M = fmaxf(M, g_m[s * N_TOK + row]);
    float L = 0.0f, w[NSPLIT];
#pragma unroll
    for (int s = 0; s < NSPLIT; s++) {
        w[s] = exp2f(g_m[s * N_TOK + row] - M);
        L += g_l[s * N_TOK + row] * w[s];
    }
    float4 acc = make_float4(0.f, 0.f, 0.f, 0.f);
#pragma unroll
    for (int s = 0; s < NSPLIT; s++) {
        float4 v = *(const float4*)&g_opart[(size_t)(s * N_TOK + row) * D_OUT + c4];
        acc.x = fmaf(v.x, w[s], acc.x);
        acc.y = fmaf(v.y, w[s], acc.y);
        acc.z = fmaf(v.z, w[s], acc.z);
        acc.w = fmaf(v.w, w[s], acc.w);
    }
    float inv = 1.0f / L;
    acc.x *= inv; acc.y *= inv; acc.z *= inv; acc.w *= inv;
    *(float4*)&out[(size_t)row * D_OUT + c4] = acc;
}

// ---------------- launch -----------------------------------------------------
extern "C" void kernel_launch(void* const* d_in, const int* in_sizes, int n_in,
                              void* d_out, int out_size) {
    const float* x  = (const float*)d_in[0];
    const float* Wk = (const float*)d_in[1];   // Q side (reference swap)
    const float* Wq = (const float*)d_in[2];   // K side
    const float* Wv = (const float*)d_in[3];
    float* out = (float*)d_out;

    cudaFuncSetAttribute(attn_kernel,
                         cudaFuncAttributeMaxDynamicSharedMemorySize, SMEM_TOTAL);

    proj_kernel<<<dim3(128, 3), 256>>>(x, Wk, Wq, Wv);
    transpose_v_kernel<<<dim3(N_TOK / 32, D_OUT / 32), 256>>>();
    attn_kernel<<<dim3(NSPLIT, 64), 128, SMEM_TOTAL>>>();
    merge_kernel<<<(N_TOK * 16) / 256, 256>>>(out);
}

// round 5
// speedup vs baseline: 2.8569x; 1.2205x over previous
#include <cuda_runtime.h>
#include <cuda_bf16.h>
#include <cstdint>
#include <math.h>

#define N_TOK   8192
#define D_INP   768
#define D_OUT   64
#define NSPLIT  4
#define KPS     (N_TOK / NSPLIT)    // 2048 keys per split
#define BN      64                  // keys per tile
#define NT      (KPS / BN)          // 32 tiles

// ---------------- scratch (device globals) --------------------------------
__device__ __align__(16) uint16_t g_xhi[N_TOK * D_INP];
__device__ __align__(16) uint16_t g_xlo[N_TOK * D_INP];
__device__ __align__(16) uint16_t g_whi[3 * D_INP * D_OUT];
__device__ __align__(16) uint16_t g_wlo[3 * D_INP * D_OUT];
__device__ __align__(16) uint32_t g_qhi[N_TOK * 32];   // bf16x2 pairs, [tok][32]
__device__ __align__(16) uint32_t g_qlo[N_TOK * 32];
__device__ __align__(16) uint32_t g_khi[N_TOK * 32];
__device__ __align__(16) uint32_t g_klo[N_TOK * 32];
__device__ __align__(16) float    g_wv [N_TOK * D_OUT];
__device__ __align__(16) uint16_t g_vThi[D_OUT * N_TOK];  // [dim][tok]
__device__ __align__(16) uint16_t g_vTlo[D_OUT * N_TOK];
__device__ float g_opart[NSPLIT * N_TOK * D_OUT];
__device__ float g_m[NSPLIT * N_TOK];   // log2-domain row max
__device__ float g_l[NSPLIT * N_TOK];

#define QSCALE 0.1803368801111372f     // (1/8) * log2(e)

// ---------------- helpers --------------------------------------------------
__device__ __forceinline__ void cvt_pair(float x, float y,
                                         uint32_t& hi, uint32_t& lo) {
    __nv_bfloat162 H = __floats2bfloat162_rn(x, y);
    float rx = x - __bfloat162float(H.x);
    float ry = y - __bfloat162float(H.y);
    __nv_bfloat162 L = __floats2bfloat162_rn(rx, ry);
    hi = *reinterpret_cast<uint32_t*>(&H);
    lo = *reinterpret_cast<uint32_t*>(&L);
}

__device__ __forceinline__ void mma16816(float* d, const uint32_t* a,
                                         uint32_t b0, uint32_t b1) {
    asm volatile(
        "mma.sync.aligned.m16n8k16.row.col.f32.bf16.bf16.f32 "
        "{%0,%1,%2,%3}, {%4,%5,%6,%7}, {%8,%9}, {%0,%1,%2,%3};\n"
        : "+f"(d[0]), "+f"(d[1]), "+f"(d[2]), "+f"(d[3])
        : "r"(a[0]), "r"(a[1]), "r"(a[2]), "r"(a[3]), "r"(b0), "r"(b1));
}

__device__ __forceinline__ uint32_t smem_u32(const void* p) {
    uint32_t a;
    asm("{ .reg .u64 t; cvta.to.shared.u64 t, %1; cvt.u32.u64 %0, t; }"
        : "=r"(a) : "l"(p));
    return a;
}

#define LDSM4(r0, r1, r2, r3, a) \
    asm volatile("ldmatrix.sync.aligned.m8n8.x4.shared.b16 {%0,%1,%2,%3}, [%4];" \
                 : "=r"(r0), "=r"(r1), "=r"(r2), "=r"(r3) : "r"(a))
#define LDSM4T(r0, r1, r2, r3, a) \
    asm volatile("ldmatrix.sync.aligned.m8n8.x4.trans.shared.b16 {%0,%1,%2,%3}, [%4];" \
                 : "=r"(r0), "=r"(r1), "=r"(r2), "=r"(r3) : "r"(a))

#define CP_ASYNC16(d, s) \
    asm volatile("cp.async.cg.shared.global [%0], [%1], 16;" \
                 :: "r"(d), "l"(s) : "memory")
#define CP_COMMIT() asm volatile("cp.async.commit_group;" ::: "memory")
#define CP_WAIT1()  asm volatile("cp.async.wait_group 1;" ::: "memory")
#define CP_WAIT0()  asm volatile("cp.async.wait_group 0;" ::: "memory")

// ---------------- split kernels ---------------------------------------------
__global__ __launch_bounds__(256)
void split_x_kernel(const float* __restrict__ x) {
    int i4 = blockIdx.x * 256 + threadIdx.x;      // one float4 each
    float4 v = ((const float4*)x)[i4];
    uint32_t h0, l0, h1, l1;
    cvt_pair(v.x, v.y, h0, l0);
    cvt_pair(v.z, v.w, h1, l1);
    ((uint32_t*)g_xhi)[i4 * 2]     = h0;
    ((uint32_t*)g_xhi)[i4 * 2 + 1] = h1;
    ((uint32_t*)g_xlo)[i4 * 2]     = l0;
    ((uint32_t*)g_xlo)[i4 * 2 + 1] = l1;
}

__global__ __launch_bounds__(256)
void split_w_kernel(const float* __restrict__ w0,
                    const float* __restrict__ w1,
                    const float* __restrict__ w2) {
    const float* W = (blockIdx.y == 0) ? w0 : (blockIdx.y == 1) ? w1 : w2;
    int i4 = blockIdx.x * 256 + threadIdx.x;
    size_t base = (size_t)blockIdx.y * (D_INP * D_OUT / 4);
    float4 v = ((const float4*)W)[i4];
    uint32_t h0, l0, h1, l1;
    cvt_pair(v.x, v.y, h0, l0);
    cvt_pair(v.z, v.w, h1, l1);
    ((uint32_t*)g_whi)[(base + i4) * 2]     = h0;
    ((uint32_t*)g_whi)[(base + i4) * 2 + 1] = h1;
    ((uint32_t*)g_wlo)[(base + i4) * 2]     = l0;
    ((uint32_t*)g_wlo)[(base + i4) * 2 + 1] = l1;
}

// ---------------- projection via split-bf16 mma -----------------------------
// O[row0..+128, 0..64) = X @ W ; 12 K-chunks of 64, 2-stage cp.async.
#define PXH 0
#define PXL 18432
#define PWH 36864
#define PWL 46080
#define PSTAGE 55296
#define PSM_TOTAL (2 * PSTAGE)    // 110592

extern __shared__ char psm[];

__device__ __forceinline__ void proj_copy_chunk(uint32_t stg, int kc, int widx,
                                                int row0, int tid) {
#pragma unroll
    for (int it = 0; it < 8; it++) {
        int id = it * 128 + tid;              // 0..1023
        int row = id >> 3, cc = id & 7;
        uint32_t doff = row * 144 + cc * 16;
        const char* sx = (const char*)(g_xhi + (size_t)(row0 + row) * D_INP + kc * 64) + cc * 16;
        CP_ASYNC16(stg + PXH + doff, sx);
        const char* sl = (const char*)(g_xlo + (size_t)(row0 + row) * D_INP + kc * 64) + cc * 16;
        CP_ASYNC16(stg + PXL + doff, sl);
    }
#pragma unroll
    for (int it = 0; it < 4; it++) {
        int id = it * 128 + tid;              // 0..511
        int row = id >> 3, cc = id & 7;
        uint32_t doff = row * 144 + cc * 16;
        const char* sh = (const char*)(g_whi + (size_t)widx * (D_INP * D_OUT)
                                       + (size_t)(kc * 64 + row) * D_OUT) + cc * 16;
        CP_ASYNC16(stg + PWH + doff, sh);
        const char* sl = (const char*)(g_wlo + (size_t)widx * (D_INP * D_OUT)
                                       + (size_t)(kc * 64 + row) * D_OUT) + cc * 16;
        CP_ASYNC16(stg + PWL + doff, sl);
    }
}

__global__ __launch_bounds__(128, 2)
void proj_mma_kernel() {
    const int tid = threadIdx.x;
    const int w = tid >> 5, lane = tid & 31;
    const int r = lane >> 2, c = lane & 3;
    const int g = lane >> 3, lr = lane & 7;
    // A / trans-B ldmatrix lane offset: g0:(row+0,col0) g1:(row+8,col0)
    //                                    g2:(row+0,col16) g3:(row+8,col16)
    const uint32_t aoff = ((g & 1) * 8 + lr) * 144 + (g >> 1) * 16;
    const int widx = blockIdx.y;
    const int row0 = blockIdx.x * 128;
    const uint32_t sb = smem_u32(psm);

    float o[2][8][4];
#pragma unroll
    for (int mf = 0; mf < 2; mf++)
#pragma unroll
        for (int nb = 0; nb < 8; nb++)
#pragma unroll
            for (int j = 0; j < 4; j++) o[mf][nb][j] = 0.0f;

    proj_copy_chunk(sb, 0, widx, row0, tid);
    CP_COMMIT();

    for (int kc = 0; kc < 12; kc++) {
        if (kc + 1 < 12) {
            proj_copy_chunk(sb + ((kc + 1) & 1) * PSTAGE, kc + 1, widx, row0, tid);
            CP_COMMIT();
            CP_WAIT1();
        } else {
            CP_WAIT0();
        }
        __syncthreads();
        const uint32_t stg = sb + (kc & 1) * PSTAGE;

#pragma unroll
        for (int kb = 0; kb < 4; kb++) {
            uint32_t ah[2][4], al[2][4];
#pragma unroll
            for (int mf = 0; mf < 2; mf++) {
                uint32_t a = stg + PXH + (w * 32 + mf * 16) * 144 + kb * 32 + aoff;
                LDSM4(ah[mf][0], ah[mf][1], ah[mf][2], ah[mf][3], a);
                LDSM4(al[mf][0], al[mf][1], al[mf][2], al[mf][3], a + (PXL - PXH));
            }
#pragma unroll
            for (int nbp = 0; nbp < 4; nbp++) {
                uint32_t b = stg + PWH + kb * 16 * 144 + nbp * 32 + aoff;
                uint32_t h0, h1, h2, h3, l0, l1, l2, l3;
                LDSM4T(h0, h1, h2, h3, b);
                LDSM4T(l0, l1, l2, l3, b + (PWL - PWH));
#pragma unroll
                for (int mf = 0; mf < 2; mf++) {
                    mma16816(o[mf][2 * nbp],     ah[mf], h0, h1);
                    mma16816(o[mf][2 * nbp],     ah[mf], l0, l1);
                    mma16816(o[mf][2 * nbp],     al[mf], h0, h1);
                    mma16816(o[mf][2 * nbp + 1], ah[mf], h2, h3);
                    mma16816(o[mf][2 * nbp + 1], ah[mf], l2, l3);
                    mma16816(o[mf][2 * nbp + 1], al[mf], h2, h3);
                }
            }
        }
        __syncthreads();
    }

    // epilogue
    if (widx < 2) {
        uint32_t* HI = (widx == 0) ? g_qhi : g_khi;
        uint32_t* LO = (widx == 0) ? g_qlo : g_klo;
        const float sc = (widx == 0) ? QSCALE : 1.0f;
#pragma unroll
        for (int mf = 0; mf < 2; mf++) {
            int ra = row0 + w * 32 + mf * 16 + r;
            int rb = ra + 8;
#pragma unroll
            for (int nb = 0; nb < 8; nb++) {
                int pi = nb * 4 + c;
                uint32_t h, l;
                cvt_pair(o[mf][nb][0] * sc, o[mf][nb][1] * sc, h, l);
                HI[ra * 32 + pi] = h; LO[ra * 32 + pi] = l;
                cvt_pair(o[mf][nb][2] * sc, o[mf][nb][3] * sc, h, l);
                HI[rb * 32 + pi] = h; LO[rb * 32 + pi] = l;
            }
        }
    } else {
#pragma unroll
        for (int mf = 0; mf < 2; mf++) {
            int ra = row0 + w * 32 + mf * 16 + r;
            int rb = ra + 8;
#pragma unroll
            for (int nb = 0; nb < 8; nb++) {
                int cc = nb * 8 + 2 * c;
                *(float2*)&g_wv[(size_t)ra * D_OUT + cc] =
                    make_float2(o[mf][nb][0], o[mf][nb][1]);
                *(float2*)&g_wv[(size_t)rb * D_OUT + cc] =
                    make_float2(o[mf][nb][2], o[mf][nb][3]);
            }
        }
    }
}

// ---------------- V transpose + bf16 split ---------------------------------
__global__ __launch_bounds__(256)
void transpose_v_kernel() {
    __shared__ float tile[32][33];
    int r0 = blockIdx.x * 32;   // token
    int c0 = blockIdx.y * 32;   // dim
    int tx = threadIdx.x & 31, ty = threadIdx.x >> 5;
#pragma unroll
    for (int i = 0; i < 4; i++)
        tile[ty + i * 8][tx] = g_wv[(size_t)(r0 + ty + i * 8) * D_OUT + c0 + tx];
    __syncthreads();
#pragma unroll
    for (int i = 0; i < 4; i++) {
        float v = tile[tx][ty + i * 8];
        __nv_bfloat16 h = __float2bfloat16_rn(v);
        float rr = v - __bfloat162float(h);
        __nv_bfloat16 lo = __float2bfloat16_rn(rr);
        int dim = c0 + ty + i * 8, tok = r0 + tx;
        g_vThi[(size_t)dim * N_TOK + tok] = *reinterpret_cast<uint16_t*>(&h);
        g_vTlo[(size_t)dim * N_TOK + tok] = *reinterpret_cast<uint16_t*>(&lo);
    }
}

// ---------------- flash attention -------------------------------------------
#define TILE_B 9216                  // 64 rows * 144 B
#define OFF_KHI 0
#define OFF_KLO TILE_B
#define OFF_VHI (2 * TILE_B)
#define OFF_VLO (3 * TILE_B)
#define BUF_B   (4 * TILE_B)         // 36864
#define STAGES  3
#define SMEM_TOTAL (STAGES * BUF_B)  // 110592

extern __shared__ char dsm[];

__device__ __forceinline__ void copy_tile_async(uint32_t sbuf, int k0, int tid) {
#pragma unroll
    for (int it = 0; it < 4; it++) {
        int id = it * 128 + tid;          // 0..511
        int row = id >> 3, cc = id & 7;
        uint32_t doff = row * 144 + cc * 16;
        CP_ASYNC16(sbuf + OFF_KHI + doff,
                   (const char*)g_khi + (size_t)(k0 + row) * 128 + cc * 16);
        CP_ASYNC16(sbuf + OFF_KLO + doff,
                   (const char*)g_klo + (size_t)(k0 + row) * 128 + cc * 16);
        CP_ASYNC16(sbuf + OFF_VHI + doff,
                   (const char*)g_vThi + (size_t)row * (N_TOK * 2) + (size_t)k0 * 2 + cc * 16);
        CP_ASYNC16(sbuf + OFF_VLO + doff,
                   (const char*)g_vTlo + (size_t)row * (N_TOK * 2) + (size_t)k0 * 2 + cc * 16);
    }
}

__global__ __launch_bounds__(128, 2)
void attn_kernel() {
    const int tid = threadIdx.x;
    const int w = tid >> 5, lane = tid & 31;
    const int r = lane >> 2, c = lane & 3;
    const int g = lane >> 3, lr = lane & 7;
    // B-frag ldmatrix lane offset: g0:(row+0,col0) g1:(row+0,col16)
    //                              g2:(row+8,col0) g3:(row+8,col16)
    const uint32_t boff = ((g >> 1) * 8 + lr) * 144 + (g & 1) * 16;
    const int split = blockIdx.x;
    const int q0 = blockIdx.y * 128;
    const uint32_t sb = smem_u32(dsm);

    // ---- Q fragments (2 m-frags x hi/lo), resident all kernel ----
    uint32_t qh[2][4][4], ql[2][4][4];
#pragma unroll
    for (int mf = 0; mf < 2; mf++) {
        int ra = q0 + w * 32 + mf * 16 + r;
        int rb = ra + 8;
#pragma unroll
        for (int kb = 0; kb < 4; kb++) {
            int base = kb * 8 + c;
            qh[mf][kb][0] = g_qhi[ra * 32 + base];
            qh[mf][kb][1] = g_qhi[rb * 32 + base];
            qh[mf][kb][2] = g_qhi[ra * 32 + base + 4];
            qh[mf][kb][3] = g_qhi[rb * 32 + base + 4];
            ql[mf][kb][0] = g_qlo[ra * 32 + base];
            ql[mf][kb][1] = g_qlo[rb * 32 + base];
            ql[mf][kb][2] = g_qlo[ra * 32 + base + 4];
            ql[mf][kb][3] = g_qlo[rb * 32 + base + 4];
        }
    }

    float o[2][8][4];
#pragma unroll
    for (int mf = 0; mf < 2; mf++)
#pragma unroll
        for (int nb = 0; nb < 8; nb++)
#pragma unroll
            for (int j = 0; j < 4; j++) o[mf][nb][j] = 0.0f;
    float m[4] = {-1e30f, -1e30f, -1e30f, -1e30f};
    float l[4] = {0.0f, 0.0f, 0.0f, 0.0f};

    const int kbase = split * KPS;
    copy_tile_async(sb, kbase, tid);
    CP_COMMIT();
    copy_tile_async(sb + BUF_B, kbase + BN, tid);
    CP_COMMIT();

    int stage = 0;
    for (int t = 0; t < NT; t++) {
        CP_WAIT1();                       // tile t resident
        __syncthreads();
        const uint32_t bu = sb + stage * BUF_B;

        // ---- S = Q Kᵀ (3-term split), ldmatrix B ----
        float s[2][8][4];
#pragma unroll
        for (int mf = 0; mf < 2; mf++)
#pragma unroll
            for (int nb = 0; nb < 8; nb++)
#pragma unroll
                for (int j = 0; j < 4; j++) s[mf][nb][j] = 0.0f;

#pragma unroll
        for (int kb = 0; kb < 4; kb++) {
#pragma unroll
            for (int nbp = 0; nbp < 4; nbp++) {
                uint32_t a = bu + OFF_KHI + nbp * (16 * 144) + kb * 32 + boff;
                uint32_t h0, h1, h2, h3, l0, l1, l2, l3;
                LDSM4(h0, h1, h2, h3, a);
                LDSM4(l0, l1, l2, l3, a + TILE_B);
#pragma unroll
                for (int mf = 0; mf < 2; mf++) {
                    mma16816(s[mf][2 * nbp],     qh[mf][kb], h0, h1);
                    mma16816(s[mf][2 * nbp],     qh[mf][kb], l0, l1);
                    mma16816(s[mf][2 * nbp],     ql[mf][kb], h0, h1);
                    mma16816(s[mf][2 * nbp + 1], qh[mf][kb], h2, h3);
                    mma16816(s[mf][2 * nbp + 1], qh[mf][kb], l2, l3);
                    mma16816(s[mf][2 * nbp + 1], ql[mf][kb], h2, h3);
                }
            }
        }

        // ---- online softmax (interleaved, exp2 domain) ----
        float mx[4] = {-1e30f, -1e30f, -1e30f, -1e30f};
#pragma unroll
        for (int mf = 0; mf < 2; mf++)
#pragma unroll
            for (int nb = 0; nb < 8; nb++) {
                mx[mf * 2]     = fmaxf(mx[mf * 2],     fmaxf(s[mf][nb][0], s[mf][nb][1]));
                mx[mf * 2 + 1] = fmaxf(mx[mf * 2 + 1], fmaxf(s[mf][nb][2], s[mf][nb][3]));
            }
#pragma unroll
        for (int i = 0; i < 4; i++)
            mx[i] = fmaxf(mx[i], __shfl_xor_sync(0xffffffffu, mx[i], 1));
#pragma unroll
        for (int i = 0; i < 4; i++)
            mx[i] = fmaxf(mx[i], __shfl_xor_sync(0xffffffffu, mx[i], 2));

        float alpha[4];
#pragma unroll
        for (int i = 0; i < 4; i++) {
            float nm = fmaxf(m[i], mx[i]);
            alpha[i] = exp2f(m[i] - nm);
            m[i] = nm;
        }

        float rs[4] = {0.0f, 0.0f, 0.0f, 0.0f};
#pragma unroll
        for (int mf = 0; mf < 2; mf++)
#pragma unroll
            for (int nb = 0; nb < 8; nb++) {
                s[mf][nb][0] = exp2f(s[mf][nb][0] - m[mf * 2]);
                s[mf][nb][1] = exp2f(s[mf][nb][1] - m[mf * 2]);
                s[mf][nb][2] = exp2f(s[mf][nb][2] - m[mf * 2 + 1]);
                s[mf][nb][3] = exp2f(s[mf][nb][3] - m[mf * 2 + 1]);
                rs[mf * 2]     += s[mf][nb][0] + s[mf][nb][1];
                rs[mf * 2 + 1] += s[mf][nb][2] + s[mf][nb][3];
            }
#pragma unroll
        for (int i = 0; i < 4; i++)
            rs[i] += __shfl_xor_sync(0xffffffffu, rs[i], 1);
#pragma unroll
        for (int i = 0; i < 4; i++)
            rs[i] += __shfl_xor_sync(0xffffffffu, rs[i], 2);
#pragma unroll
        for (int i = 0; i < 4; i++)
            l[i] = l[i] * alpha[i] + rs[i];

#pragma unroll
        for (int mf = 0; mf < 2; mf++)
#pragma unroll
            for (int nb = 0; nb < 8; nb++) {
                o[mf][nb][0] *= alpha[mf * 2]; o[mf][nb][1] *= alpha[mf * 2];
                o[mf][nb][2] *= alpha[mf * 2 + 1]; o[mf][nb][3] *= alpha[mf * 2 + 1];
            }

        // ---- O += P V (P in registers, ldmatrix B) ----
#pragma unroll
        for (int kb = 0; kb < 4; kb++) {
            uint32_t ah[2][4], al[2][4];
#pragma unroll
            for (int mf = 0; mf < 2; mf++) {
                cvt_pair(s[mf][2 * kb][0],     s[mf][2 * kb][1],     ah[mf][0], al[mf][0]);
                cvt_pair(s[mf][2 * kb][2],     s[mf][2 * kb][3],     ah[mf][1], al[mf][1]);
                cvt_pair(s[mf][2 * kb + 1][0], s[mf][2 * kb + 1][1], ah[mf][2], al[mf][2]);
                cvt_pair(s[mf][2 * kb + 1][2], s[mf][2 * kb + 1][3], ah[mf][3], al[mf][3]);
            }
#pragma unroll
            for (int nbp = 0; nbp < 4; nbp++) {
                uint32_t a = bu + OFF_VHI + nbp * (16 * 144) + kb * 32 + boff;
                uint32_t h0, h1, h2, h3, l0, l1, l2, l3;
                LDSM4(h0, h1, h2, h3, a);
                LDSM4(l0, l1, l2, l3, a + TILE_B);
#pragma unroll
                for (int mf = 0; mf < 2; mf++) {
                    mma16816(o[mf][2 * nbp],     ah[mf], h0, h1);
                    mma16816(o[mf][2 * nbp],     ah[mf], l0, l1);
                    mma16816(o[mf][2 * nbp],     al[mf], h0, h1);
                    mma16816(o[mf][2 * nbp + 1], ah[mf], h2, h3);
                    mma16816(o[mf][2 * nbp + 1], ah[mf], l2, l3);
                    mma16816(o[mf][2 * nbp + 1], al[mf], h2, h3);
                }
            }
        }

        // prefetch t+2 into stage (t+2)%3 (== stage of t-1, safe past barrier)
        if (t + 2 < NT) {
            int ps = stage + 2; if (ps >= STAGES) ps -= STAGES;
            copy_tile_async(sb + ps * BUF_B, kbase + (t + 2) * BN, tid);
        }
        CP_COMMIT();
        if (++stage == STAGES) stage = 0;
    }

    // ---- epilogue ----
#pragma unroll
    for (int mf = 0; mf < 2; mf++) {
        size_t orow0 = (size_t)split * N_TOK + q0 + w * 32 + mf * 16 + r;
        size_t orow8 = orow0 + 8;
#pragma unroll
        for (int nb = 0; nb < 8; nb++) {
            int cc = nb * 8 + 2 * c;
            *(float2*)&g_opart[orow0 * D_OUT + cc] =
                make_float2(o[mf][nb][0], o[mf][nb][1]);
            *(float2*)&g_opart[orow8 * D_OUT + cc] =
                make_float2(o[mf][nb][2], o[mf][nb][3]);
        }
        if (c == 0) {
            g_m[orow0] = m[mf * 2];     g_l[orow0] = l[mf * 2];
            g_m[orow8] = m[mf * 2 + 1]; g_l[orow8] = l[mf * 2 + 1];
        }
    }
}

// ---------------- merge (log2-domain m) -------------------------------------
__global__ __launch_bounds__(256)
void merge_kernel(float* __restrict__ out) {
    int idx = blockIdx.x * blockDim.x + threadIdx.x;
    int row = idx >> 4;
    int c4 = (idx & 15) * 4;

    float M = -1e30f;
#pragma unroll
    for (int s = 0; s < NSPLIT; s++) M = fmaxf(M, g_m[s * N_TOK + row]);
    float L = 0.0f, w[NSPLIT];
#pragma unroll
    for (int s = 0; s < NSPLIT; s++) {
        w[s] = exp2f(g_m[s * N_TOK + row] - M);
        L += g_l[s * N_TOK + row] * w[s];
    }
    float4 acc = make_float4(0.f, 0.f, 0.f, 0.f);
#pragma unroll
    for (int s = 0; s < NSPLIT; s++) {
        float4 v = *(const float4*)&g_opart[(size_t)(s * N_TOK + row) * D_OUT + c4];
        acc.x = fmaf(v.x, w[s], acc.x);
        acc.y = fmaf(v.y, w[s], acc.y);
        acc.z = fmaf(v.z, w[s], acc.z);
        acc.w = fmaf(v.w, w[s], acc.w);
    }
    float inv = 1.0f / L;
    acc.x *= inv; acc.y *= inv; acc.z *= inv; acc.w *= inv;
    *(float4*)&out[(size_t)row * D_OUT + c4] = acc;
}

// ---------------- launch ------------------------------------------------------
extern "C" void kernel_launch(void* const* d_in, const int* in_sizes, int n_in,
                              void* d_out, int out_size) {
    const float* x  = (const float*)d_in[0];
    const float* Wk = (const float*)d_in[1];   // Q side (reference swap)
    const float* Wq = (const float*)d_in[2];   // K side
    const float* Wv = (const float*)d_in[3];
    float* out = (float*)d_out;

    cudaFuncSetAttribute(proj_mma_kernel,
                         cudaFuncAttributeMaxDynamicSharedMemorySize, PSM_TOTAL);
    cudaFuncSetAttribute(attn_kernel,
                         cudaFuncAttributeMaxDynamicSharedMemorySize, SMEM_TOTAL);

    split_x_kernel<<<N_TOK * D_INP / 4 / 256, 256>>>(x);
    split_w_kernel<<<dim3(D_INP * D_OUT / 4 / 256, 3), 256>>>(Wk, Wq, Wv);
    proj_mma_kernel<<<dim3(64, 3), 128, PSM_TOTAL>>>();
    transpose_v_kernel<<<dim3(N_TOK / 32, D_OUT / 32), 256>>>();
    attn_kernel<<<dim3(NSPLIT, 64), 128, SMEM_TOTAL>>>();
    merge_kernel<<<(N_TOK * 16) / 256, 256>>>(out);
}

// round 6
// speedup vs baseline: 2.8635x; 1.0023x over previous
#include <cuda_runtime.h>
#include <cuda_bf16.h>
#include <cstdint>
#include <math.h>

#define N_TOK   8192
#define D_INP   768
#define D_OUT   64
#define NSPLIT  4
#define KPS     (N_TOK / NSPLIT)    // 2048 keys per split
#define BN      64                  // keys per tile
#define NT      (KPS / BN)          // 32 tiles

// ---------------- scratch (device globals) --------------------------------
__device__ __align__(16) uint16_t g_xhi[N_TOK * D_INP];
__device__ __align__(16) uint16_t g_xlo[N_TOK * D_INP];
__device__ __align__(16) uint16_t g_whi[3 * D_INP * D_OUT];
__device__ __align__(16) uint16_t g_wlo[3 * D_INP * D_OUT];
__device__ __align__(16) uint32_t g_qhi[N_TOK * 32];   // bf16x2 pairs, [tok][32]
__device__ __align__(16) uint32_t g_qlo[N_TOK * 32];
__device__ __align__(16) uint32_t g_khi[N_TOK * 32];
__device__ __align__(16) uint32_t g_klo[N_TOK * 32];
__device__ __align__(16) float    g_wv [N_TOK * D_OUT];
__device__ __align__(16) uint16_t g_vThi[D_OUT * N_TOK];  // [dim][tok]
__device__ __align__(16) uint16_t g_vTlo[D_OUT * N_TOK];
__device__ float g_opart[NSPLIT * N_TOK * D_OUT];
__device__ float g_m[NSPLIT * N_TOK];   // log2-domain row max
__device__ float g_l[NSPLIT * N_TOK];

#define QSCALE 0.1803368801111372f     // (1/8) * log2(e)

// ---------------- helpers --------------------------------------------------
__device__ __forceinline__ void cvt_pair(float x, float y,
                                         uint32_t& hi, uint32_t& lo) {
    __nv_bfloat162 H = __floats2bfloat162_rn(x, y);
    float rx = x - __bfloat162float(H.x);
    float ry = y - __bfloat162float(H.y);
    __nv_bfloat162 L = __floats2bfloat162_rn(rx, ry);
    hi = *reinterpret_cast<uint32_t*>(&H);
    lo = *reinterpret_cast<uint32_t*>(&L);
}

__device__ __forceinline__ void mma16816(float* d, const uint32_t* a,
                                         uint32_t b0, uint32_t b1) {
    asm volatile(
        "mma.sync.aligned.m16n8k16.row.col.f32.bf16.bf16.f32 "
        "{%0,%1,%2,%3}, {%4,%5,%6,%7}, {%8,%9}, {%0,%1,%2,%3};\n"
        : "+f"(d[0]), "+f"(d[1]), "+f"(d[2]), "+f"(d[3])
        : "r"(a[0]), "r"(a[1]), "r"(a[2]), "r"(a[3]), "r"(b0), "r"(b1));
}

__device__ __forceinline__ uint32_t smem_u32(const void* p) {
    uint32_t a;
    asm("{ .reg .u64 t; cvta.to.shared.u64 t, %1; cvt.u32.u64 %0, t; }"
        : "=r"(a) : "l"(p));
    return a;
}

#define LDSM4(r0, r1, r2, r3, a) \
    asm volatile("ldmatrix.sync.aligned.m8n8.x4.shared.b16 {%0,%1,%2,%3}, [%4];" \
                 : "=r"(r0), "=r"(r1), "=r"(r2), "=r"(r3) : "r"(a))
#define LDSM4T(r0, r1, r2, r3, a) \
    asm volatile("ldmatrix.sync.aligned.m8n8.x4.trans.shared.b16 {%0,%1,%2,%3}, [%4];" \
                 : "=r"(r0), "=r"(r1), "=r"(r2), "=r"(r3) : "r"(a))

#define CP_ASYNC16(d, s) \
    asm volatile("cp.async.cg.shared.global [%0], [%1], 16;" \
                 :: "r"(d), "l"(s) : "memory")
#define CP_COMMIT() asm volatile("cp.async.commit_group;" ::: "memory")
#define CP_WAIT1()  asm volatile("cp.async.wait_group 1;" ::: "memory")
#define CP_WAIT0()  asm volatile("cp.async.wait_group 0;" ::: "memory")

// ---------------- split kernels ---------------------------------------------
__global__ __launch_bounds__(256)
void split_x_kernel(const float* __restrict__ x) {
    int i4 = blockIdx.x * 256 + threadIdx.x;      // one float4 each
    float4 v = ((const float4*)x)[i4];
    uint32_t h0, l0, h1, l1;
    cvt_pair(v.x, v.y, h0, l0);
    cvt_pair(v.z, v.w, h1, l1);
    ((uint32_t*)g_xhi)[i4 * 2]     = h0;
    ((uint32_t*)g_xhi)[i4 * 2 + 1] = h1;
    ((uint32_t*)g_xlo)[i4 * 2]     = l0;
    ((uint32_t*)g_xlo)[i4 * 2 + 1] = l1;
}

__global__ __launch_bounds__(256)
void split_w_kernel(const float* __restrict__ w0,
                    const float* __restrict__ w1,
                    const float* __restrict__ w2) {
    const float* W = (blockIdx.y == 0) ? w0 : (blockIdx.y == 1) ? w1 : w2;
    int i4 = blockIdx.x * 256 + threadIdx.x;
    size_t base = (size_t)blockIdx.y * (D_INP * D_OUT / 4);
    float4 v = ((const float4*)W)[i4];
    uint32_t h0, l0, h1, l1;
    cvt_pair(v.x, v.y, h0, l0);
    cvt_pair(v.z, v.w, h1, l1);
    ((uint32_t*)g_whi)[(base + i4) * 2]     = h0;
    ((uint32_t*)g_whi)[(base + i4) * 2 + 1] = h1;
    ((uint32_t*)g_wlo)[(base + i4) * 2]     = l0;
    ((uint32_t*)g_wlo)[(base + i4) * 2 + 1] = l1;
}

// ---------------- projection via split-bf16 mma -----------------------------
#define PXH 0
#define PXL 18432
#define PWH 36864
#define PWL 46080
#define PSTAGE 55296
#define PSM_TOTAL (2 * PSTAGE)    // 110592

extern __shared__ char psm[];

__device__ __forceinline__ void proj_copy_chunk(uint32_t stg, int kc, int widx,
                                                int row0, int tid) {
#pragma unroll
    for (int it = 0; it < 8; it++) {
        int id = it * 128 + tid;              // 0..1023
        int row = id >> 3, cc = id & 7;
        uint32_t doff = row * 144 + cc * 16;
        const char* sx = (const char*)(g_xhi + (size_t)(row0 + row) * D_INP + kc * 64) + cc * 16;
        CP_ASYNC16(stg + PXH + doff, sx);
        const char* sl = (const char*)(g_xlo + (size_t)(row0 + row) * D_INP + kc * 64) + cc * 16;
        CP_ASYNC16(stg + PXL + doff, sl);
    }
#pragma unroll
    for (int it = 0; it < 4; it++) {
        int id = it * 128 + tid;              // 0..511
        int row = id >> 3, cc = id & 7;
        uint32_t doff = row * 144 + cc * 16;
        const char* sh = (const char*)(g_whi + (size_t)widx * (D_INP * D_OUT)
                                       + (size_t)(kc * 64 + row) * D_OUT) + cc * 16;
        CP_ASYNC16(stg + PWH + doff, sh);
        const char* sl = (const char*)(g_wlo + (size_t)widx * (D_INP * D_OUT)
                                       + (size_t)(kc * 64 + row) * D_OUT) + cc * 16;
        CP_ASYNC16(stg + PWL + doff, sl);
    }
}

__global__ __launch_bounds__(128, 2)
void proj_mma_kernel() {
    const int tid = threadIdx.x;
    const int w = tid >> 5, lane = tid & 31;
    const int r = lane >> 2, c = lane & 3;
    const int g = lane >> 3, lr = lane & 7;
    const uint32_t aoff = ((g & 1) * 8 + lr) * 144 + (g >> 1) * 16;
    const int widx = blockIdx.y;
    const int row0 = blockIdx.x * 128;
    const uint32_t sb = smem_u32(psm);

    float o[2][8][4];
#pragma unroll
    for (int mf = 0; mf < 2; mf++)
#pragma unroll
        for (int nb = 0; nb < 8; nb++)
#pragma unroll
            for (int j = 0; j < 4; j++) o[mf][nb][j] = 0.0f;

    proj_copy_chunk(sb, 0, widx, row0, tid);
    CP_COMMIT();

    for (int kc = 0; kc < 12; kc++) {
        if (kc + 1 < 12) {
            proj_copy_chunk(sb + ((kc + 1) & 1) * PSTAGE, kc + 1, widx, row0, tid);
            CP_COMMIT();
            CP_WAIT1();
        } else {
            CP_WAIT0();
        }
        __syncthreads();
        const uint32_t stg = sb + (kc & 1) * PSTAGE;

#pragma unroll
        for (int kb = 0; kb < 4; kb++) {
            uint32_t ah[2][4], al[2][4];
#pragma unroll
            for (int mf = 0; mf < 2; mf++) {
                uint32_t a = stg + PXH + (w * 32 + mf * 16) * 144 + kb * 32 + aoff;
                LDSM4(ah[mf][0], ah[mf][1], ah[mf][2], ah[mf][3], a);
                LDSM4(al[mf][0], al[mf][1], al[mf][2], al[mf][3], a + (PXL - PXH));
            }
#pragma unroll
            for (int nbp = 0; nbp < 4; nbp++) {
                uint32_t b = stg + PWH + kb * 16 * 144 + nbp * 32 + aoff;
                uint32_t h0, h1, h2, h3, l0, l1, l2, l3;
                LDSM4T(h0, h1, h2, h3, b);
                LDSM4T(l0, l1, l2, l3, b + (PWL - PWH));
#pragma unroll
                for (int mf = 0; mf < 2; mf++) {
                    mma16816(o[mf][2 * nbp],     ah[mf], h0, h1);
                    mma16816(o[mf][2 * nbp],     ah[mf], l0, l1);
                    mma16816(o[mf][2 * nbp],     al[mf], h0, h1);
                    mma16816(o[mf][2 * nbp + 1], ah[mf], h2, h3);
                    mma16816(o[mf][2 * nbp + 1], ah[mf], l2, l3);
                    mma16816(o[mf][2 * nbp + 1], al[mf], h2, h3);
                }
            }
        }
        __syncthreads();
    }

    if (widx < 2) {
        uint32_t* HI = (widx == 0) ? g_qhi : g_khi;
        uint32_t* LO = (widx == 0) ? g_qlo : g_klo;
        const float sc = (widx == 0) ? QSCALE : 1.0f;
#pragma unroll
        for (int mf = 0; mf < 2; mf++) {
            int ra = row0 + w * 32 + mf * 16 + r;
            int rb = ra + 8;
#pragma unroll
            for (int nb = 0; nb < 8; nb++) {
                int pi = nb * 4 + c;
                uint32_t h, l;
                cvt_pair(o[mf][nb][0] * sc, o[mf][nb][1] * sc, h, l);
                HI[ra * 32 + pi] = h; LO[ra * 32 + pi] = l;
                cvt_pair(o[mf][nb][2] * sc, o[mf][nb][3] * sc, h, l);
                HI[rb * 32 + pi] = h; LO[rb * 32 + pi] = l;
            }
        }
    } else {
#pragma unroll
        for (int mf = 0; mf < 2; mf++) {
            int ra = row0 + w * 32 + mf * 16 + r;
            int rb = ra + 8;
#pragma unroll
            for (int nb = 0; nb < 8; nb++) {
                int cc = nb * 8 + 2 * c;
                *(float2*)&g_wv[(size_t)ra * D_OUT + cc] =
                    make_float2(o[mf][nb][0], o[mf][nb][1]);
                *(float2*)&g_wv[(size_t)rb * D_OUT + cc] =
                    make_float2(o[mf][nb][2], o[mf][nb][3]);
            }
        }
    }
}

// ---------------- V transpose + bf16 split ---------------------------------
__global__ __launch_bounds__(256)
void transpose_v_kernel() {
    __shared__ float tile[32][33];
    int r0 = blockIdx.x * 32;   // token
    int c0 = blockIdx.y * 32;   // dim
    int tx = threadIdx.x & 31, ty = threadIdx.x >> 5;
#pragma unroll
    for (int i = 0; i < 4; i++)
        tile[ty + i * 8][tx] = g_wv[(size_t)(r0 + ty + i * 8) * D_OUT + c0 + tx];
    __syncthreads();
#pragma unroll
    for (int i = 0; i < 4; i++) {
        float v = tile[tx][ty + i * 8];
        __nv_bfloat16 h = __float2bfloat16_rn(v);
        float rr = v - __bfloat162float(h);
        __nv_bfloat16 lo = __float2bfloat16_rn(rr);
        int dim = c0 + ty + i * 8, tok = r0 + tx;
        g_vThi[(size_t)dim * N_TOK + tok] = *reinterpret_cast<uint16_t*>(&h);
        g_vTlo[(size_t)dim * N_TOK + tok] = *reinterpret_cast<uint16_t*>(&lo);
    }
}

// ---------------- flash attention -------------------------------------------
// grid (NSPLIT, 64), block 256 (8 warps, mf=1: warp w owns rows q0+16w..+15).
#define TILE_B 9216                  // 64 rows * 144 B
#define OFF_KHI 0
#define OFF_KLO TILE_B
#define OFF_VHI (2 * TILE_B)
#define OFF_VLO (3 * TILE_B)
#define BUF_B   (4 * TILE_B)         // 36864
#define STAGES  3
#define SMEM_TOTAL (STAGES * BUF_B)  // 110592

extern __shared__ char dsm[];

__device__ __forceinline__ void copy_tile_async(uint32_t sbuf, int k0, int tid) {
#pragma unroll
    for (int it = 0; it < 2; it++) {
        int id = it * 256 + tid;          // 0..511
        int row = id >> 3, cc = id & 7;
        uint32_t doff = row * 144 + cc * 16;
        CP_ASYNC16(sbuf + OFF_KHI + doff,
                   (const char*)g_khi + (size_t)(k0 + row) * 128 + cc * 16);
        CP_ASYNC16(sbuf + OFF_KLO + doff,
                   (const char*)g_klo + (size_t)(k0 + row) * 128 + cc * 16);
        CP_ASYNC16(sbuf + OFF_VHI + doff,
                   (const char*)g_vThi + (size_t)row * (N_TOK * 2) + (size_t)k0 * 2 + cc * 16);
        CP_ASYNC16(sbuf + OFF_VLO + doff,
                   (const char*)g_vTlo + (size_t)row * (N_TOK * 2) + (size_t)k0 * 2 + cc * 16);
    }
}

__global__ __launch_bounds__(256, 2)
void attn_kernel() {
    const int tid = threadIdx.x;
    const int w = tid >> 5, lane = tid & 31;
    const int r = lane >> 2, c = lane & 3;
    const int g = lane >> 3, lr = lane & 7;
    const uint32_t boff = ((g >> 1) * 8 + lr) * 144 + (g & 1) * 16;
    const int split = blockIdx.x;
    const int q0 = blockIdx.y * 128;
    const uint32_t sb = smem_u32(dsm);

    // ---- Q fragments (hi/lo), resident all kernel ----
    uint32_t qh[4][4], ql[4][4];
    {
        int ra = q0 + w * 16 + r;
        int rb = ra + 8;
#pragma unroll
        for (int kb = 0; kb < 4; kb++) {
            int base = kb * 8 + c;
            qh[kb][0] = g_qhi[ra * 32 + base];
            qh[kb][1] = g_qhi[rb * 32 + base];
            qh[kb][2] = g_qhi[ra * 32 + base + 4];
            qh[kb][3] = g_qhi[rb * 32 + base + 4];
            ql[kb][0] = g_qlo[ra * 32 + base];
            ql[kb][1] = g_qlo[rb * 32 + base];
            ql[kb][2] = g_qlo[ra * 32 + base + 4];
            ql[kb][3] = g_qlo[rb * 32 + base + 4];
        }
    }

    float o[8][4];
#pragma unroll
    for (int nb = 0; nb < 8; nb++)
#pragma unroll
        for (int j = 0; j < 4; j++) o[nb][j] = 0.0f;
    float m0 = -1e30f, m1 = -1e30f, l0v = 0.0f, l1v = 0.0f;

    const int kbase = split * KPS;
    copy_tile_async(sb, kbase, tid);
    CP_COMMIT();
    copy_tile_async(sb + BUF_B, kbase + BN, tid);
    CP_COMMIT();

    int stage = 0;
    for (int t = 0; t < NT; t++) {
        CP_WAIT1();
        __syncthreads();
        const uint32_t bu = sb + stage * BUF_B;

        // ---- S = Q Kᵀ (3-term split), ldmatrix B ----
        float s[8][4];
#pragma unroll
        for (int nb = 0; nb < 8; nb++)
#pragma unroll
            for (int j = 0; j < 4; j++) s[nb][j] = 0.0f;

#pragma unroll
        for (int kb = 0; kb < 4; kb++) {
#pragma unroll
            for (int nbp = 0; nbp < 4; nbp++) {
                uint32_t a = bu + OFF_KHI + nbp * (16 * 144) + kb * 32 + boff;
                uint32_t h0, h1, h2, h3, l0, l1, l2, l3;
                LDSM4(h0, h1, h2, h3, a);
                LDSM4(l0, l1, l2, l3, a + TILE_B);
                mma16816(s[2 * nbp],     qh[kb], h0, h1);
                mma16816(s[2 * nbp],     qh[kb], l0, l1);
                mma16816(s[2 * nbp],     ql[kb], h0, h1);
                mma16816(s[2 * nbp + 1], qh[kb], h2, h3);
                mma16816(s[2 * nbp + 1], qh[kb], l2, l3);
                mma16816(s[2 * nbp + 1], ql[kb], h2, h3);
            }
        }

        // ---- online softmax (exp2 domain) ----
        float mx0 = -1e30f, mx1 = -1e30f;
#pragma unroll
        for (int nb = 0; nb < 8; nb++) {
            mx0 = fmaxf(mx0, fmaxf(s[nb][0], s[nb][1]));
            mx1 = fmaxf(mx1, fmaxf(s[nb][2], s[nb][3]));
        }
        mx0 = fmaxf(mx0, __shfl_xor_sync(0xffffffffu, mx0, 1));
        mx1 = fmaxf(mx1, __shfl_xor_sync(0xffffffffu, mx1, 1));
        mx0 = fmaxf(mx0, __shfl_xor_sync(0xffffffffu, mx0, 2));
        mx1 = fmaxf(mx1, __shfl_xor_sync(0xffffffffu, mx1, 2));

        float nm0 = fmaxf(m0, mx0), nm1 = fmaxf(m1, mx1);
        float a0 = exp2f(m0 - nm0), a1 = exp2f(m1 - nm1);
        m0 = nm0; m1 = nm1;

        float rs0 = 0.0f, rs1 = 0.0f;
#pragma unroll
        for (int nb = 0; nb < 8; nb++) {
            s[nb][0] = exp2f(s[nb][0] - nm0);
            s[nb][1] = exp2f(s[nb][1] - nm0);
            s[nb][2] = exp2f(s[nb][2] - nm1);
            s[nb][3] = exp2f(s[nb][3] - nm1);
            rs0 += s[nb][0] + s[nb][1];
            rs1 += s[nb][2] + s[nb][3];
        }
        rs0 += __shfl_xor_sync(0xffffffffu, rs0, 1);
        rs1 += __shfl_xor_sync(0xffffffffu, rs1, 1);
        rs0 += __shfl_xor_sync(0xffffffffu, rs0, 2);
        rs1 += __shfl_xor_sync(0xffffffffu, rs1, 2);
        l0v = l0v * a0 + rs0;
        l1v = l1v * a1 + rs1;

#pragma unroll
        for (int nb = 0; nb < 8; nb++) {
            o[nb][0] *= a0; o[nb][1] *= a0;
            o[nb][2] *= a1; o[nb][3] *= a1;
        }

        // ---- O += P V (P in registers, ldmatrix B) ----
#pragma unroll
        for (int kb = 0; kb < 4; kb++) {
            uint32_t ah[4], al[4];
            cvt_pair(s[2 * kb][0],     s[2 * kb][1],     ah[0], al[0]);
            cvt_pair(s[2 * kb][2],     s[2 * kb][3],     ah[1], al[1]);
            cvt_pair(s[2 * kb + 1][0], s[2 * kb + 1][1], ah[2], al[2]);
            cvt_pair(s[2 * kb + 1][2], s[2 * kb + 1][3], ah[3], al[3]);
#pragma unroll
            for (int nbp = 0; nbp < 4; nbp++) {
                uint32_t a = bu + OFF_VHI + nbp * (16 * 144) + kb * 32 + boff;
                uint32_t h0, h1, h2, h3, l0, l1, l2, l3;
                LDSM4(h0, h1, h2, h3, a);
                LDSM4(l0, l1, l2, l3, a + TILE_B);
                mma16816(o[2 * nbp],     ah, h0, h1);
                mma16816(o[2 * nbp],     ah, l0, l1);
                mma16816(o[2 * nbp],     al, h0, h1);
                mma16816(o[2 * nbp + 1], ah, h2, h3);
                mma16816(o[2 * nbp + 1], ah, l2, l3);
                mma16816(o[2 * nbp + 1], al, h2, h3);
            }
        }

        if (t + 2 < NT) {
            int ps = stage + 2; if (ps >= STAGES) ps -= STAGES;
            copy_tile_async(sb + ps * BUF_B, kbase + (t + 2) * BN, tid);
        }
        CP_COMMIT();
        if (++stage == STAGES) stage = 0;
    }

    // ---- epilogue ----
    {
        size_t orow0 = (size_t)split * N_TOK + q0 + w * 16 + r;
        size_t orow8 = orow0 + 8;
#pragma unroll
        for (int nb = 0; nb < 8; nb++) {
            int cc = nb * 8 + 2 * c;
            *(float2*)&g_opart[orow0 * D_OUT + cc] = make_float2(o[nb][0], o[nb][1]);
            *(float2*)&g_opart[orow8 * D_OUT + cc] = make_float2(o[nb][2], o[nb][3]);
        }
        if (c == 0) {
            g_m[orow0] = m0; g_l[orow0] = l0v;
            g_m[orow8] = m1; g_l[orow8] = l1v;
        }
    }
}

// ---------------- merge (log2-domain m) -------------------------------------
__global__ __launch_bounds__(256)
void merge_kernel(float* __restrict__ out) {
    int idx = blockIdx.x * blockDim.x + threadIdx.x;
    int row = idx >> 4;
    int c4 = (idx & 15) * 4;

    float M = -1e30f;
#pragma unroll
    for (int s = 0; s < NSPLIT; s++) M = fmaxf(M, g_m[s * N_TOK + row]);
    float L = 0.0f, w[NSPLIT];
#pragma unroll
    for (int s = 0; s < NSPLIT; s++) {
        w[s] = exp2f(g_m[s * N_TOK + row] - M);
        L += g_l[s * N_TOK + row] * w[s];
    }
    float4 acc = make_float4(0.f, 0.f, 0.f, 0.f);
#pragma unroll
    for (int s = 0; s < NSPLIT; s++) {
        float4 v = *(const float4*)&g_opart[(size_t)(s * N_TOK + row) * D_OUT + c4];
        acc.x = fmaf(v.x, w[s], acc.x);
        acc.y = fmaf(v.y, w[s], acc.y);
        acc.z = fmaf(v.z, w[s], acc.z);
        acc.w = fmaf(v.w, w[s], acc.w);
    }
    float inv = 1.0f / L;
    acc.x *= inv; acc.y *= inv; acc.z *= inv; acc.w *= inv;
    *(float4*)&out[(size_t)row * D_OUT + c4] = acc;
}

// ---------------- launch ------------------------------------------------------
extern "C" void kernel_launch(void* const* d_in, const int* in_sizes, int n_in,
                              void* d_out, int out_size) {
    const float* x  = (const float*)d_in[0];
    const float* Wk = (const float*)d_in[1];   // Q side (reference swap)
    const float* Wq = (const float*)d_in[2];   // K side
    const float* Wv = (const float*)d_in[3];
    float* out = (float*)d_out;

    cudaFuncSetAttribute(proj_mma_kernel,
                         cudaFuncAttributeMaxDynamicSharedMemorySize, PSM_TOTAL);
    cudaFuncSetAttribute(attn_kernel,
                         cudaFuncAttributeMaxDynamicSharedMemorySize, SMEM_TOTAL);

    split_x_kernel<<<N_TOK * D_INP / 4 / 256, 256>>>(x);
    split_w_kernel<<<dim3(D_INP * D_OUT / 4 / 256, 3), 256>>>(Wk, Wq, Wv);
    proj_mma_kernel<<<dim3(64, 3), 128, PSM_TOTAL>>>();
    transpose_v_kernel<<<dim3(N_TOK / 32, D_OUT / 32), 256>>>();
    attn_kernel<<<dim3(NSPLIT, 64), 256, SMEM_TOTAL>>>();
    merge_kernel<<<(N_TOK * 16) / 256, 256>>>(out);
}

// round 7
// speedup vs baseline: 2.9138x; 1.0176x over previous
#include <cuda_runtime.h>
#include <cuda_bf16.h>
#include <cstdint>
#include <math.h>

#define N_TOK   8192
#define D_INP   768
#define D_OUT   64
#define NSPLIT  9                   // uneven key-ranges
#define BN      64                  // keys per tile
#define NTILES_ALL 128              // 8192 / 64
#define GRID_A  288                 // persistent attn CTAs (2 items each)

// ---------------- scratch (device globals) --------------------------------
__device__ __align__(16) uint16_t g_xhi[N_TOK * D_INP];
__device__ __align__(16) uint16_t g_xlo[N_TOK * D_INP];
__device__ __align__(16) uint16_t g_whi[3 * D_INP * D_OUT];
__device__ __align__(16) uint16_t g_wlo[3 * D_INP * D_OUT];
__device__ __align__(16) uint32_t g_qhi[N_TOK * 32];   // bf16x2 pairs, [tok][32]
__device__ __align__(16) uint32_t g_qlo[N_TOK * 32];
__device__ __align__(16) uint32_t g_khi[N_TOK * 32];
__device__ __align__(16) uint32_t g_klo[N_TOK * 32];
__device__ __align__(16) uint32_t g_vhi[N_TOK * 32];   // V, natural [tok][dim]
__device__ __align__(16) uint32_t g_vlo[N_TOK * 32];
__device__ float g_opart[NSPLIT * N_TOK * D_OUT];
__device__ float g_m[NSPLIT * N_TOK];   // log2-domain row max
__device__ float g_l[NSPLIT * N_TOK];

#define QSCALE 0.1803368801111372f     // (1/8) * log2(e)

// ---------------- helpers --------------------------------------------------
__device__ __forceinline__ void cvt_pair(float x, float y,
                                         uint32_t& hi, uint32_t& lo) {
    __nv_bfloat162 H = __floats2bfloat162_rn(x, y);
    float rx = x - __bfloat162float(H.x);
    float ry = y - __bfloat162float(H.y);
    __nv_bfloat162 L = __floats2bfloat162_rn(rx, ry);
    hi = *reinterpret_cast<uint32_t*>(&H);
    lo = *reinterpret_cast<uint32_t*>(&L);
}

__device__ __forceinline__ void mma16816(float* d, const uint32_t* a,
                                         uint32_t b0, uint32_t b1) {
    asm volatile(
        "mma.sync.aligned.m16n8k16.row.col.f32.bf16.bf16.f32 "
        "{%0,%1,%2,%3}, {%4,%5,%6,%7}, {%8,%9}, {%0,%1,%2,%3};\n"
        : "+f"(d[0]), "+f"(d[1]), "+f"(d[2]), "+f"(d[3])
        : "r"(a[0]), "r"(a[1]), "r"(a[2]), "r"(a[3]), "r"(b0), "r"(b1));
}

__device__ __forceinline__ uint32_t smem_u32(const void* p) {
    uint32_t a;
    asm("{ .reg .u64 t; cvta.to.shared.u64 t, %1; cvt.u32.u64 %0, t; }"
        : "=r"(a) : "l"(p));
    return a;
}

#define LDSM4(r0, r1, r2, r3, a) \
    asm volatile("ldmatrix.sync.aligned.m8n8.x4.shared.b16 {%0,%1,%2,%3}, [%4];" \
                 : "=r"(r0), "=r"(r1), "=r"(r2), "=r"(r3) : "r"(a))
#define LDSM4T(r0, r1, r2, r3, a) \
    asm volatile("ldmatrix.sync.aligned.m8n8.x4.trans.shared.b16 {%0,%1,%2,%3}, [%4];" \
                 : "=r"(r0), "=r"(r1), "=r"(r2), "=r"(r3) : "r"(a))

#define CP_ASYNC16(d, s) \
    asm volatile("cp.async.cg.shared.global [%0], [%1], 16;" \
                 :: "r"(d), "l"(s) : "memory")
#define CP_COMMIT() asm volatile("cp.async.commit_group;" ::: "memory")
#define CP_WAIT1()  asm volatile("cp.async.wait_group 1;" ::: "memory")
#define CP_WAIT0()  asm volatile("cp.async.wait_group 0;" ::: "memory")

// ---------------- split kernels ---------------------------------------------
__global__ __launch_bounds__(256)
void split_x_kernel(const float* __restrict__ x) {
    int i4 = blockIdx.x * 256 + threadIdx.x;
    float4 v = ((const float4*)x)[i4];
    uint32_t h0, l0, h1, l1;
    cvt_pair(v.x, v.y, h0, l0);
    cvt_pair(v.z, v.w, h1, l1);
    ((uint32_t*)g_xhi)[i4 * 2]     = h0;
    ((uint32_t*)g_xhi)[i4 * 2 + 1] = h1;
    ((uint32_t*)g_xlo)[i4 * 2]     = l0;
    ((uint32_t*)g_xlo)[i4 * 2 + 1] = l1;
}

__global__ __launch_bounds__(256)
void split_w_kernel(const float* __restrict__ w0,
                    const float* __restrict__ w1,
                    const float* __restrict__ w2) {
    const float* W = (blockIdx.y == 0) ? w0 : (blockIdx.y == 1) ? w1 : w2;
    int i4 = blockIdx.x * 256 + threadIdx.x;
    size_t base = (size_t)blockIdx.y * (D_INP * D_OUT / 4);
    float4 v = ((const float4*)W)[i4];
    uint32_t h0, l0, h1, l1;
    cvt_pair(v.x, v.y, h0, l0);
    cvt_pair(v.z, v.w, h1, l1);
    ((uint32_t*)g_whi)[(base + i4) * 2]     = h0;
    ((uint32_t*)g_whi)[(base + i4) * 2 + 1] = h1;
    ((uint32_t*)g_wlo)[(base + i4) * 2]     = l0;
    ((uint32_t*)g_wlo)[(base + i4) * 2 + 1] = l1;
}

// ---------------- projection via split-bf16 mma -----------------------------
#define PXH 0
#define PXL 18432
#define PWH 36864
#define PWL 46080
#define PSTAGE 55296
#define PSM_TOTAL (2 * PSTAGE)    // 110592

extern __shared__ char psm[];

__device__ __forceinline__ void proj_copy_chunk(uint32_t stg, int kc, int widx,
                                                int row0, int tid) {
#pragma unroll
    for (int it = 0; it < 8; it++) {
        int id = it * 128 + tid;              // 0..1023
        int row = id >> 3, cc = id & 7;
        uint32_t doff = row * 144 + cc * 16;
        const char* sx = (const char*)(g_xhi + (size_t)(row0 + row) * D_INP + kc * 64) + cc * 16;
        CP_ASYNC16(stg + PXH + doff, sx);
        const char* sl = (const char*)(g_xlo + (size_t)(row0 + row) * D_INP + kc * 64) + cc * 16;
        CP_ASYNC16(stg + PXL + doff, sl);
    }
#pragma unroll
    for (int it = 0; it < 4; it++) {
        int id = it * 128 + tid;              // 0..511
        int row = id >> 3, cc = id & 7;
        uint32_t doff = row * 144 + cc * 16;
        const char* sh = (const char*)(g_whi + (size_t)widx * (D_INP * D_OUT)
                                       + (size_t)(kc * 64 + row) * D_OUT) + cc * 16;
        CP_ASYNC16(stg + PWH + doff, sh);
        const char* sl = (const char*)(g_wlo + (size_t)widx * (D_INP * D_OUT)
                                       + (size_t)(kc * 64 + row) * D_OUT) + cc * 16;
        CP_ASYNC16(stg + PWL + doff, sl);
    }
}

__global__ __launch_bounds__(128, 2)
void proj_mma_kernel() {
    const int tid = threadIdx.x;
    const int w = tid >> 5, lane = tid & 31;
    const int r = lane >> 2, c = lane & 3;
    const int g = lane >> 3, lr = lane & 7;
    const uint32_t aoff = ((g & 1) * 8 + lr) * 144 + (g >> 1) * 16;
    const int widx = blockIdx.y;
    const int row0 = blockIdx.x * 128;
    const uint32_t sb = smem_u32(psm);

    float o[2][8][4];
#pragma unroll
    for (int mf = 0; mf < 2; mf++)
#pragma unroll
        for (int nb = 0; nb < 8; nb++)
#pragma unroll
            for (int j = 0; j < 4; j++) o[mf][nb][j] = 0.0f;

    proj_copy_chunk(sb, 0, widx, row0, tid);
    CP_COMMIT();

    for (int kc = 0; kc < 12; kc++) {
        if (kc + 1 < 12) {
            proj_copy_chunk(sb + ((kc + 1) & 1) * PSTAGE, kc + 1, widx, row0, tid);
            CP_COMMIT();
            CP_WAIT1();
        } else {
            CP_WAIT0();
        }
        __syncthreads();
        const uint32_t stg = sb + (kc & 1) * PSTAGE;

#pragma unroll
        for (int kb = 0; kb < 4; kb++) {
            uint32_t ah[2][4], al[2][4];
#pragma unroll
            for (int mf = 0; mf < 2; mf++) {
                uint32_t a = stg + PXH + (w * 32 + mf * 16) * 144 + kb * 32 + aoff;
                LDSM4(ah[mf][0], ah[mf][1], ah[mf][2], ah[mf][3], a);
                LDSM4(al[mf][0], al[mf][1], al[mf][2], al[mf][3], a + (PXL - PXH));
            }
#pragma unroll
            for (int nbp = 0; nbp < 4; nbp++) {
                uint32_t b = stg + PWH + kb * 16 * 144 + nbp * 32 + aoff;
                uint32_t h0, h1, h2, h3, l0, l1, l2, l3;
                LDSM4T(h0, h1, h2, h3, b);
                LDSM4T(l0, l1, l2, l3, b + (PWL - PWH));
#pragma unroll
                for (int mf = 0; mf < 2; mf++) {
                    mma16816(o[mf][2 * nbp],     ah[mf], h0, h1);
                    mma16816(o[mf][2 * nbp],     ah[mf], l0, l1);
                    mma16816(o[mf][2 * nbp],     al[mf], h0, h1);
                    mma16816(o[mf][2 * nbp + 1], ah[mf], h2, h3);
                    mma16816(o[mf][2 * nbp + 1], ah[mf], l2, l3);
                    mma16816(o[mf][2 * nbp + 1], al[mf], h2, h3);
                }
            }
        }
        __syncthreads();
    }

    // epilogue: all three projections stored as split bf16 (Q scaled)
    uint32_t* HI = (widx == 0) ? g_qhi : (widx == 1) ? g_khi : g_vhi;
    uint32_t* LO = (widx == 0) ? g_qlo : (widx == 1) ? g_klo : g_vlo;
    const float sc = (widx == 0) ? QSCALE : 1.0f;
#pragma unroll
    for (int mf = 0; mf < 2; mf++) {
        int ra = row0 + w * 32 + mf * 16 + r;
        int rb = ra + 8;
#pragma unroll
        for (int nb = 0; nb < 8; nb++) {
            int pi = nb * 4 + c;
            uint32_t h, l;
            cvt_pair(o[mf][nb][0] * sc, o[mf][nb][1] * sc, h, l);
            HI[ra * 32 + pi] = h; LO[ra * 32 + pi] = l;
            cvt_pair(o[mf][nb][2] * sc, o[mf][nb][3] * sc, h, l);
            HI[rb * 32 + pi] = h; LO[rb * 32 + pi] = l;
        }
    }
}

// ---------------- flash attention (persistent, 2 items/CTA) -----------------
#define TILE_B 9216                  // 64 rows * 144 B
#define OFF_KHI 0
#define OFF_KLO TILE_B
#define OFF_VHI (2 * TILE_B)
#define OFF_VLO (3 * TILE_B)
#define BUF_B   (4 * TILE_B)         // 36864
#define STAGES  3
#define SMEM_TOTAL (STAGES * BUF_B)  // 110592

extern __shared__ char dsm[];

__device__ __forceinline__ void copy_tile_async(uint32_t sbuf, int k0, int tid) {
#pragma unroll
    for (int it = 0; it < 2; it++) {
        int id = it * 256 + tid;          // 0..511
        int row = id >> 3, cc = id & 7;
        uint32_t doff = row * 144 + cc * 16;
        CP_ASYNC16(sbuf + OFF_KHI + doff,
                   (const char*)g_khi + (size_t)(k0 + row) * 128 + cc * 16);
        CP_ASYNC16(sbuf + OFF_KLO + doff,
                   (const char*)g_klo + (size_t)(k0 + row) * 128 + cc * 16);
        CP_ASYNC16(sbuf + OFF_VHI + doff,
                   (const char*)g_vhi + (size_t)(k0 + row) * 128 + cc * 16);
        CP_ASYNC16(sbuf + OFF_VLO + doff,
                   (const char*)g_vlo + (size_t)(k0 + row) * 128 + cc * 16);
    }
}

__global__ __launch_bounds__(256, 2)
void attn_kernel() {
    const int tid = threadIdx.x;
    const int w = tid >> 5, lane = tid & 31;
    const int r = lane >> 2, c = lane & 3;
    const int g = lane >> 3, lr = lane & 7;
    // non-trans B (K tile, S phase)
    const uint32_t boff = ((g >> 1) * 8 + lr) * 144 + (g & 1) * 16;
    // trans B (V tile, PV phase) — same mapping as proj's W loads
    const uint32_t toff = ((g & 1) * 8 + lr) * 144 + (g >> 1) * 16;
    const uint32_t sb = smem_u32(dsm);

    for (int item = 0; item < 2; item++) {
        const int wi = blockIdx.x + item * GRID_A;     // 0..575
        const int qb = wi / NSPLIT;
        const int ri = wi - qb * NSPLIT;
        const int tile0 = (ri * NTILES_ALL) / NSPLIT;
        const int ntile = ((ri + 1) * NTILES_ALL) / NSPLIT - tile0;
        const int q0 = qb * 128;

        // ---- Q fragments (hi/lo) ----
        uint32_t qh[4][4], ql[4][4];
        {
            int ra = q0 + w * 16 + r;
            int rb = ra + 8;
#pragma unroll
            for (int kb = 0; kb < 4; kb++) {
                int base = kb * 8 + c;
                qh[kb][0] = g_qhi[ra * 32 + base];
                qh[kb][1] = g_qhi[rb * 32 + base];
                qh[kb][2] = g_qhi[ra * 32 + base + 4];
                qh[kb][3] = g_qhi[rb * 32 + base + 4];
                ql[kb][0] = g_qlo[ra * 32 + base];
                ql[kb][1] = g_qlo[rb * 32 + base];
                ql[kb][2] = g_qlo[ra * 32 + base + 4];
                ql[kb][3] = g_qlo[rb * 32 + base + 4];
            }
        }

        float o[8][4];
#pragma unroll
        for (int nb = 0; nb < 8; nb++)
#pragma unroll
            for (int j = 0; j < 4; j++) o[nb][j] = 0.0f;
        float m0 = -1e30f, m1 = -1e30f, l0v = 0.0f, l1v = 0.0f;

        copy_tile_async(sb, tile0 * BN, tid);
        CP_COMMIT();
        if (ntile > 1)
            copy_tile_async(sb + BUF_B, (tile0 + 1) * BN, tid);
        CP_COMMIT();

        int stage = 0;
        for (int t = 0; t < ntile; t++) {
            CP_WAIT1();
            __syncthreads();
            const uint32_t bu = sb + stage * BUF_B;

            // ---- S = Q Kᵀ (3-term split) ----
            float s[8][4];
#pragma unroll
            for (int nb = 0; nb < 8; nb++)
#pragma unroll
                for (int j = 0; j < 4; j++) s[nb][j] = 0.0f;

#pragma unroll
            for (int kb = 0; kb < 4; kb++) {
#pragma unroll
                for (int nbp = 0; nbp < 4; nbp++) {
                    uint32_t a = bu + OFF_KHI + nbp * (16 * 144) + kb * 32 + boff;
                    uint32_t h0, h1, h2, h3, l0, l1, l2, l3;
                    LDSM4(h0, h1, h2, h3, a);
                    LDSM4(l0, l1, l2, l3, a + TILE_B);
                    mma16816(s[2 * nbp],     qh[kb], h0, h1);
                    mma16816(s[2 * nbp],     qh[kb], l0, l1);
                    mma16816(s[2 * nbp],     ql[kb], h0, h1);
                    mma16816(s[2 * nbp + 1], qh[kb], h2, h3);
                    mma16816(s[2 * nbp + 1], qh[kb], l2, l3);
                    mma16816(s[2 * nbp + 1], ql[kb], h2, h3);
                }
            }

            // ---- online softmax (exp2 domain) ----
            float mx0 = -1e30f, mx1 = -1e30f;
#pragma unroll
            for (int nb = 0; nb < 8; nb++) {
                mx0 = fmaxf(mx0, fmaxf(s[nb][0], s[nb][1]));
                mx1 = fmaxf(mx1, fmaxf(s[nb][2], s[nb][3]));
            }
            mx0 = fmaxf(mx0, __shfl_xor_sync(0xffffffffu, mx0, 1));
            mx1 = fmaxf(mx1, __shfl_xor_sync(0xffffffffu, mx1, 1));
            mx0 = fmaxf(mx0, __shfl_xor_sync(0xffffffffu, mx0, 2));
            mx1 = fmaxf(mx1, __shfl_xor_sync(0xffffffffu, mx1, 2));

            float nm0 = fmaxf(m0, mx0), nm1 = fmaxf(m1, mx1);
            float a0 = exp2f(m0 - nm0), a1 = exp2f(m1 - nm1);
            m0 = nm0; m1 = nm1;

            float rs0 = 0.0f, rs1 = 0.0f;
#pragma unroll
            for (int nb = 0; nb < 8; nb++) {
                s[nb][0] = exp2f(s[nb][0] - nm0);
                s[nb][1] = exp2f(s[nb][1] - nm0);
                s[nb][2] = exp2f(s[nb][2] - nm1);
                s[nb][3] = exp2f(s[nb][3] - nm1);
                rs0 += s[nb][0] + s[nb][1];
                rs1 += s[nb][2] + s[nb][3];
            }
            rs0 += __shfl_xor_sync(0xffffffffu, rs0, 1);
            rs1 += __shfl_xor_sync(0xffffffffu, rs1, 1);
            rs0 += __shfl_xor_sync(0xffffffffu, rs0, 2);
            rs1 += __shfl_xor_sync(0xffffffffu, rs1, 2);
            l0v = l0v * a0 + rs0;
            l1v = l1v * a1 + rs1;

#pragma unroll
            for (int nb = 0; nb < 8; nb++) {
                o[nb][0] *= a0; o[nb][1] *= a0;
                o[nb][2] *= a1; o[nb][3] *= a1;
            }

            // ---- O += P V (V via ldmatrix.trans on natural layout) ----
#pragma unroll
            for (int kb = 0; kb < 4; kb++) {
                uint32_t ah[4], al[4];
                cvt_pair(s[2 * kb][0],     s[2 * kb][1],     ah[0], al[0]);
                cvt_pair(s[2 * kb][2],     s[2 * kb][3],     ah[1], al[1]);
                cvt_pair(s[2 * kb + 1][0], s[2 * kb + 1][1], ah[2], al[2]);
                cvt_pair(s[2 * kb + 1][2], s[2 * kb + 1][3], ah[3], al[3]);
#pragma unroll
                for (int nbp = 0; nbp < 4; nbp++) {
                    uint32_t a = bu + OFF_VHI + kb * (16 * 144) + nbp * 32 + toff;
                    uint32_t h0, h1, h2, h3, l0, l1, l2, l3;
                    LDSM4T(h0, h1, h2, h3, a);
                    LDSM4T(l0, l1, l2, l3, a + TILE_B);
                    mma16816(o[2 * nbp],     ah, h0, h1);
                    mma16816(o[2 * nbp],     ah, l0, l1);
                    mma16816(o[2 * nbp],     al, h0, h1);
                    mma16816(o[2 * nbp + 1], ah, h2, h3);
                    mma16816(o[2 * nbp + 1], ah, l2, l3);
                    mma16816(o[2 * nbp + 1], al, h2, h3);
                }
            }

            if (t + 2 < ntile) {
                int ps = stage + 2; if (ps >= STAGES) ps -= STAGES;
                copy_tile_async(sb + ps * BUF_B, (tile0 + t + 2) * BN, tid);
            }
            CP_COMMIT();
            if (++stage == STAGES) stage = 0;
        }

        // ---- epilogue ----
        {
            size_t orow0 = (size_t)ri * N_TOK + q0 + w * 16 + r;
            size_t orow8 = orow0 + 8;
#pragma unroll
            for (int nb = 0; nb < 8; nb++) {
                int cc = nb * 8 + 2 * c;
                *(float2*)&g_opart[orow0 * D_OUT + cc] = make_float2(o[nb][0], o[nb][1]);
                *(float2*)&g_opart[orow8 * D_OUT + cc] = make_float2(o[nb][2], o[nb][3]);
            }
            if (c == 0) {
                g_m[orow0] = m0; g_l[orow0] = l0v;
                g_m[orow8] = m1; g_l[orow8] = l1v;
            }
        }

        CP_WAIT0();
        __syncthreads();     // drain before next item reuses smem
    }
}

// ---------------- merge (log2-domain m, 9 splits) ----------------------------
__global__ __launch_bounds__(256)
void merge_kernel(float* __restrict__ out) {
    int idx = blockIdx.x * blockDim.x + threadIdx.x;
    int row = idx >> 4;
    int c4 = (idx & 15) * 4;

    float M = -1e30f;
#pragma unroll
    for (int s = 0; s < NSPLIT; s++) M = fmaxf(M, g_m[s * N_TOK + row]);
    float L = 0.0f, w[NSPLIT];
#pragma unroll
    for (int s = 0; s < NSPLIT; s++) {
        w[s] = exp2f(g_m[s * N_TOK + row] - M);
        L += g_l[s * N_TOK + row] * w[s];
    }
    float4 acc = make_float4(0.f, 0.f, 0.f, 0.f);
#pragma unroll
    for (int s = 0; s < NSPLIT; s++) {
        float4 v = *(const float4*)&g_opart[(size_t)(s * N_TOK + row) * D_OUT + c4];
        acc.x = fmaf(v.x, w[s], acc.x);
        acc.y = fmaf(v.y, w[s], acc.y);
        acc.z = fmaf(v.z, w[s], acc.z);
        acc.w = fmaf(v.w, w[s], acc.w);
    }
    float inv = 1.0f / L;
    acc.x *= inv; acc.y *= inv; acc.z *= inv; acc.w *= inv;
    *(float4*)&out[(size_t)row * D_OUT + c4] = acc;
}

// ---------------- launch ------------------------------------------------------
extern "C" void kernel_launch(void* const* d_in, const int* in_sizes, int n_in,
                              void* d_out, int out_size) {
    const float* x  = (const float*)d_in[0];
    const float* Wk = (const float*)d_in[1];   // Q side (reference swap)
    const float* Wq = (const float*)d_in[2];   // K side
    const float* Wv = (const float*)d_in[3];
    float* out = (float*)d_out;

    cudaFuncSetAttribute(proj_mma_kernel,
                         cudaFuncAttributeMaxDynamicSharedMemorySize, PSM_TOTAL);
    cudaFuncSetAttribute(attn_kernel,
                         cudaFuncAttributeMaxDynamicSharedMemorySize, SMEM_TOTAL);

    split_x_kernel<<<N_TOK * D_INP / 4 / 256, 256>>>(x);
    split_w_kernel<<<dim3(D_INP * D_OUT / 4 / 256, 3), 256>>>(Wk, Wq, Wv);
    proj_mma_kernel<<<dim3(64, 3), 128, PSM_TOTAL>>>();
    attn_kernel<<<GRID_A, 256, SMEM_TOTAL>>>();
    merge_kernel<<<(N_TOK * 16) / 256, 256>>>(out);
}

// round 8
// speedup vs baseline: 3.1268x; 1.0731x over previous
#include <cuda_runtime.h>
#include <cuda_bf16.h>
#include <cstdint>
#include <math.h>

#define N_TOK   8192
#define D_INP   768
#define D_OUT   64
#define NSPLIT  9                   // uneven key-ranges
#define BN      64                  // keys per tile
#define NTILES_ALL 128              // 8192 / 64
#define GRID_A  288                 // persistent attn CTAs (2 items each)

// ---------------- scratch (device globals) --------------------------------
__device__ __align__(16) uint16_t g_xhi[N_TOK * D_INP];
__device__ __align__(16) uint16_t g_xlo[N_TOK * D_INP];
__device__ __align__(16) uint16_t g_whi[3 * D_INP * D_OUT];
__device__ __align__(16) uint16_t g_wlo[3 * D_INP * D_OUT];
__device__ __align__(16) uint32_t g_qhi[N_TOK * 32];   // bf16x2 pairs, [tok][32]
__device__ __align__(16) uint32_t g_qlo[N_TOK * 32];
__device__ __align__(16) uint32_t g_khi[N_TOK * 32];
__device__ __align__(16) uint32_t g_klo[N_TOK * 32];
__device__ __align__(16) uint32_t g_vhi[N_TOK * 32];   // V, natural [tok][dim]
__device__ __align__(16) uint32_t g_vlo[N_TOK * 32];
__device__ float g_opart[NSPLIT * N_TOK * D_OUT];
__device__ float g_l[NSPLIT * N_TOK];

#define QSCALE 0.1803368801111372f     // (1/8) * log2(e)

// ---------------- helpers --------------------------------------------------
__device__ __forceinline__ void cvt_pair(float x, float y,
                                         uint32_t& hi, uint32_t& lo) {
    __nv_bfloat162 H = __floats2bfloat162_rn(x, y);
    float rx = x - __bfloat162float(H.x);
    float ry = y - __bfloat162float(H.y);
    __nv_bfloat162 L = __floats2bfloat162_rn(rx, ry);
    hi = *reinterpret_cast<uint32_t*>(&H);
    lo = *reinterpret_cast<uint32_t*>(&L);
}

__device__ __forceinline__ void mma16816(float* d, const uint32_t* a,
                                         uint32_t b0, uint32_t b1) {
    asm volatile(
        "mma.sync.aligned.m16n8k16.row.col.f32.bf16.bf16.f32 "
        "{%0,%1,%2,%3}, {%4,%5,%6,%7}, {%8,%9}, {%0,%1,%2,%3};\n"
        : "+f"(d[0]), "+f"(d[1]), "+f"(d[2]), "+f"(d[3])
        : "r"(a[0]), "r"(a[1]), "r"(a[2]), "r"(a[3]), "r"(b0), "r"(b1));
}

__device__ __forceinline__ uint32_t smem_u32(const void* p) {
    uint32_t a;
    asm("{ .reg .u64 t; cvta.to.shared.u64 t, %1; cvt.u32.u64 %0, t; }"
        : "=r"(a) : "l"(p));
    return a;
}

#define LDSM4(r0, r1, r2, r3, a) \
    asm volatile("ldmatrix.sync.aligned.m8n8.x4.shared.b16 {%0,%1,%2,%3}, [%4];" \
                 : "=r"(r0), "=r"(r1), "=r"(r2), "=r"(r3) : "r"(a))
#define LDSM4T(r0, r1, r2, r3, a) \
    asm volatile("ldmatrix.sync.aligned.m8n8.x4.trans.shared.b16 {%0,%1,%2,%3}, [%4];" \
                 : "=r"(r0), "=r"(r1), "=r"(r2), "=r"(r3) : "r"(a))

#define CP_ASYNC16(d, s) \
    asm volatile("cp.async.cg.shared.global [%0], [%1], 16;" \
                 :: "r"(d), "l"(s) : "memory")
#define CP_COMMIT() asm volatile("cp.async.commit_group;" ::: "memory")
#define CP_WAIT1()  asm volatile("cp.async.wait_group 1;" ::: "memory")
#define CP_WAIT0()  asm volatile("cp.async.wait_group 0;" ::: "memory")

// ---------------- split kernels ---------------------------------------------
__global__ __launch_bounds__(256)
void split_x_kernel(const float* __restrict__ x) {
    int i4 = blockIdx.x * 256 + threadIdx.x;
    float4 v = ((const float4*)x)[i4];
    uint32_t h0, l0, h1, l1;
    cvt_pair(v.x, v.y, h0, l0);
    cvt_pair(v.z, v.w, h1, l1);
    ((uint32_t*)g_xhi)[i4 * 2]     = h0;
    ((uint32_t*)g_xhi)[i4 * 2 + 1] = h1;
    ((uint32_t*)g_xlo)[i4 * 2]     = l0;
    ((uint32_t*)g_xlo)[i4 * 2 + 1] = l1;
}

__global__ __launch_bounds__(256)
void split_w_kernel(const float* __restrict__ w0,
                    const float* __restrict__ w1,
                    const float* __restrict__ w2) {
    const float* W = (blockIdx.y == 0) ? w0 : (blockIdx.y == 1) ? w1 : w2;
    int i4 = blockIdx.x * 256 + threadIdx.x;
    size_t base = (size_t)blockIdx.y * (D_INP * D_OUT / 4);
    float4 v = ((const float4*)W)[i4];
    uint32_t h0, l0, h1, l1;
    cvt_pair(v.x, v.y, h0, l0);
    cvt_pair(v.z, v.w, h1, l1);
    ((uint32_t*)g_whi)[(base + i4) * 2]     = h0;
    ((uint32_t*)g_whi)[(base + i4) * 2 + 1] = h1;
    ((uint32_t*)g_wlo)[(base + i4) * 2]     = l0;
    ((uint32_t*)g_wlo)[(base + i4) * 2 + 1] = l1;
}

// ---------------- projection via split-bf16 mma -----------------------------
#define PXH 0
#define PXL 18432
#define PWH 36864
#define PWL 46080
#define PSTAGE 55296
#define PSM_TOTAL (2 * PSTAGE)    // 110592

extern __shared__ char psm[];

__device__ __forceinline__ void proj_copy_chunk(uint32_t stg, int kc, int widx,
                                                int row0, int tid) {
#pragma unroll
    for (int it = 0; it < 8; it++) {
        int id = it * 128 + tid;              // 0..1023
        int row = id >> 3, cc = id & 7;
        uint32_t doff = row * 144 + cc * 16;
        const char* sx = (const char*)(g_xhi + (size_t)(row0 + row) * D_INP + kc * 64) + cc * 16;
        CP_ASYNC16(stg + PXH + doff, sx);
        const char* sl = (const char*)(g_xlo + (size_t)(row0 + row) * D_INP + kc * 64) + cc * 16;
        CP_ASYNC16(stg + PXL + doff, sl);
    }
#pragma unroll
    for (int it = 0; it < 4; it++) {
        int id = it * 128 + tid;              // 0..511
        int row = id >> 3, cc = id & 7;
        uint32_t doff = row * 144 + cc * 16;
        const char* sh = (const char*)(g_whi + (size_t)widx * (D_INP * D_OUT)
                                       + (size_t)(kc * 64 + row) * D_OUT) + cc * 16;
        CP_ASYNC16(stg + PWH + doff, sh);
        const char* sl = (const char*)(g_wlo + (size_t)widx * (D_INP * D_OUT)
                                       + (size_t)(kc * 64 + row) * D_OUT) + cc * 16;
        CP_ASYNC16(stg + PWL + doff, sl);
    }
}

__global__ __launch_bounds__(128, 2)
void proj_mma_kernel() {
    const int tid = threadIdx.x;
    const int w = tid >> 5, lane = tid & 31;
    const int r = lane >> 2, c = lane & 3;
    const int g = lane >> 3, lr = lane & 7;
    const uint32_t aoff = ((g & 1) * 8 + lr) * 144 + (g >> 1) * 16;
    const int widx = blockIdx.y;
    const int row0 = blockIdx.x * 128;
    const uint32_t sb = smem_u32(psm);

    float o[2][8][4];
#pragma unroll
    for (int mf = 0; mf < 2; mf++)
#pragma unroll
        for (int nb = 0; nb < 8; nb++)
#pragma unroll
            for (int j = 0; j < 4; j++) o[mf][nb][j] = 0.0f;

    proj_copy_chunk(sb, 0, widx, row0, tid);
    CP_COMMIT();

    for (int kc = 0; kc < 12; kc++) {
        if (kc + 1 < 12) {
            proj_copy_chunk(sb + ((kc + 1) & 1) * PSTAGE, kc + 1, widx, row0, tid);
            CP_COMMIT();
            CP_WAIT1();
        } else {
            CP_WAIT0();
        }
        __syncthreads();
        const uint32_t stg = sb + (kc & 1) * PSTAGE;

#pragma unroll
        for (int kb = 0; kb < 4; kb++) {
            uint32_t ah[2][4], al[2][4];
#pragma unroll
            for (int mf = 0; mf < 2; mf++) {
                uint32_t a = stg + PXH + (w * 32 + mf * 16) * 144 + kb * 32 + aoff;
                LDSM4(ah[mf][0], ah[mf][1], ah[mf][2], ah[mf][3], a);
                LDSM4(al[mf][0], al[mf][1], al[mf][2], al[mf][3], a + (PXL - PXH));
            }
#pragma unroll
            for (int nbp = 0; nbp < 4; nbp++) {
                uint32_t b = stg + PWH + kb * 16 * 144 + nbp * 32 + aoff;
                uint32_t h0, h1, h2, h3, l0, l1, l2, l3;
                LDSM4T(h0, h1, h2, h3, b);
                LDSM4T(l0, l1, l2, l3, b + (PWL - PWH));
#pragma unroll
                for (int mf = 0; mf < 2; mf++) {
                    mma16816(o[mf][2 * nbp],     ah[mf], h0, h1);
                    mma16816(o[mf][2 * nbp],     ah[mf], l0, l1);
                    mma16816(o[mf][2 * nbp],     al[mf], h0, h1);
                    mma16816(o[mf][2 * nbp + 1], ah[mf], h2, h3);
                    mma16816(o[mf][2 * nbp + 1], ah[mf], l2, l3);
                    mma16816(o[mf][2 * nbp + 1], al[mf], h2, h3);
                }
            }
        }
        __syncthreads();
    }

    uint32_t* HI = (widx == 0) ? g_qhi : (widx == 1) ? g_khi : g_vhi;
    uint32_t* LO = (widx == 0) ? g_qlo : (widx == 1) ? g_klo : g_vlo;
    const float sc = (widx == 0) ? QSCALE : 1.0f;
#pragma unroll
    for (int mf = 0; mf < 2; mf++) {
        int ra = row0 + w * 32 + mf * 16 + r;
        int rb = ra + 8;
#pragma unroll
        for (int nb = 0; nb < 8; nb++) {
            int pi = nb * 4 + c;
            uint32_t h, l;
            cvt_pair(o[mf][nb][0] * sc, o[mf][nb][1] * sc, h, l);
            HI[ra * 32 + pi] = h; LO[ra * 32 + pi] = l;
            cvt_pair(o[mf][nb][2] * sc, o[mf][nb][3] * sc, h, l);
            HI[rb * 32 + pi] = h; LO[rb * 32 + pi] = l;
        }
    }
}

// ---------------- flash attention (persistent, no-max softmax) ---------------
#define TILE_B 9216                  // 64 rows * 144 B
#define OFF_KHI 0
#define OFF_KLO TILE_B
#define OFF_VHI (2 * TILE_B)
#define OFF_VLO (3 * TILE_B)
#define BUF_B   (4 * TILE_B)         // 36864
#define STAGES  3
#define SMEM_TOTAL (STAGES * BUF_B)  // 110592

extern __shared__ char dsm[];

__device__ __forceinline__ void copy_tile_async(uint32_t sbuf, int k0, int tid) {
#pragma unroll
    for (int it = 0; it < 2; it++) {
        int id = it * 256 + tid;          // 0..511
        int row = id >> 3, cc = id & 7;
        uint32_t doff = row * 144 + cc * 16;
        CP_ASYNC16(sbuf + OFF_KHI + doff,
                   (const char*)g_khi + (size_t)(k0 + row) * 128 + cc * 16);
        CP_ASYNC16(sbuf + OFF_KLO + doff,
                   (const char*)g_klo + (size_t)(k0 + row) * 128 + cc * 16);
        CP_ASYNC16(sbuf + OFF_VHI + doff,
                   (const char*)g_vhi + (size_t)(k0 + row) * 128 + cc * 16);
        CP_ASYNC16(sbuf + OFF_VLO + doff,
                   (const char*)g_vlo + (size_t)(k0 + row) * 128 + cc * 16);
    }
}

__global__ __launch_bounds__(256, 2)
void attn_kernel() {
    const int tid = threadIdx.x;
    const int w = tid >> 5, lane = tid & 31;
    const int r = lane >> 2, c = lane & 3;
    const int g = lane >> 3, lr = lane & 7;
    const uint32_t boff = ((g >> 1) * 8 + lr) * 144 + (g & 1) * 16;   // non-trans (K)
    const uint32_t toff = ((g & 1) * 8 + lr) * 144 + (g >> 1) * 16;   // trans (V)
    const uint32_t sb = smem_u32(dsm);

    for (int item = 0; item < 2; item++) {
        const int wi = blockIdx.x + item * GRID_A;     // 0..575
        const int qb = wi / NSPLIT;
        const int ri = wi - qb * NSPLIT;
        const int tile0 = (ri * NTILES_ALL) / NSPLIT;
        const int ntile = ((ri + 1) * NTILES_ALL) / NSPLIT - tile0;
        const int q0 = qb * 128;

        // ---- Q fragments (hi/lo) ----
        uint32_t qh[4][4], ql[4][4];
        {
            int ra = q0 + w * 16 + r;
            int rb = ra + 8;
#pragma unroll
            for (int kb = 0; kb < 4; kb++) {
                int base = kb * 8 + c;
                qh[kb][0] = g_qhi[ra * 32 + base];
                qh[kb][1] = g_qhi[rb * 32 + base];
                qh[kb][2] = g_qhi[ra * 32 + base + 4];
                qh[kb][3] = g_qhi[rb * 32 + base + 4];
                ql[kb][0] = g_qlo[ra * 32 + base];
                ql[kb][1] = g_qlo[rb * 32 + base];
                ql[kb][2] = g_qlo[ra * 32 + base + 4];
                ql[kb][3] = g_qlo[rb * 32 + base + 4];
            }
        }

        float o[8][4];
#pragma unroll
        for (int nb = 0; nb < 8; nb++)
#pragma unroll
            for (int j = 0; j < 4; j++) o[nb][j] = 0.0f;
        float l0v = 0.0f, l1v = 0.0f;       // per-thread partial row sums

        copy_tile_async(sb, tile0 * BN, tid);
        CP_COMMIT();
        if (ntile > 1)
            copy_tile_async(sb + BUF_B, (tile0 + 1) * BN, tid);
        CP_COMMIT();

        int stage = 0;
        for (int t = 0; t < ntile; t++) {
            CP_WAIT1();
            __syncthreads();
            const uint32_t bu = sb + stage * BUF_B;

            // ---- S = Q Kᵀ (3-term split) ----
            float s[8][4];
#pragma unroll
            for (int nb = 0; nb < 8; nb++)
#pragma unroll
                for (int j = 0; j < 4; j++) s[nb][j] = 0.0f;

#pragma unroll
            for (int kb = 0; kb < 4; kb++) {
#pragma unroll
                for (int nbp = 0; nbp < 4; nbp++) {
                    uint32_t a = bu + OFF_KHI + nbp * (16 * 144) + kb * 32 + boff;
                    uint32_t h0, h1, h2, h3, l0, l1, l2, l3;
                    LDSM4(h0, h1, h2, h3, a);
                    LDSM4(l0, l1, l2, l3, a + TILE_B);
                    mma16816(s[2 * nbp],     qh[kb], h0, h1);
                    mma16816(s[2 * nbp],     qh[kb], l0, l1);
                    mma16816(s[2 * nbp],     ql[kb], h0, h1);
                    mma16816(s[2 * nbp + 1], qh[kb], h2, h3);
                    mma16816(s[2 * nbp + 1], qh[kb], l2, l3);
                    mma16816(s[2 * nbp + 1], ql[kb], h2, h3);
                }
            }

            // ---- no-max softmax: p = exp2(s); accumulate row sums ----
#pragma unroll
            for (int nb = 0; nb < 8; nb++) {
                s[nb][0] = exp2f(s[nb][0]);
                s[nb][1] = exp2f(s[nb][1]);
                s[nb][2] = exp2f(s[nb][2]);
                s[nb][3] = exp2f(s[nb][3]);
                l0v += s[nb][0] + s[nb][1];
                l1v += s[nb][2] + s[nb][3];
            }

            // ---- O += P V (V via ldmatrix.trans on natural layout) ----
#pragma unroll
            for (int kb = 0; kb < 4; kb++) {
                uint32_t ah[4], al[4];
                cvt_pair(s[2 * kb][0],     s[2 * kb][1],     ah[0], al[0]);
                cvt_pair(s[2 * kb][2],     s[2 * kb][3],     ah[1], al[1]);
                cvt_pair(s[2 * kb + 1][0], s[2 * kb + 1][1], ah[2], al[2]);
                cvt_pair(s[2 * kb + 1][2], s[2 * kb + 1][3], ah[3], al[3]);
#pragma unroll
                for (int nbp = 0; nbp < 4; nbp++) {
                    uint32_t a = bu + OFF_VHI + kb * (16 * 144) + nbp * 32 + toff;
                    uint32_t h0, h1, h2, h3, l0, l1, l2, l3;
                    LDSM4T(h0, h1, h2, h3, a);
                    LDSM4T(l0, l1, l2, l3, a + TILE_B);
                    mma16816(o[2 * nbp],     ah, h0, h1);
                    mma16816(o[2 * nbp],     ah, l0, l1);
                    mma16816(o[2 * nbp],     al, h0, h1);
                    mma16816(o[2 * nbp + 1], ah, h2, h3);
                    mma16816(o[2 * nbp + 1], ah, l2, l3);
                    mma16816(o[2 * nbp + 1], al, h2, h3);
                }
            }

            if (t + 2 < ntile) {
                int ps = stage + 2; if (ps >= STAGES) ps -= STAGES;
                copy_tile_async(sb + ps * BUF_B, (tile0 + t + 2) * BN, tid);
            }
            CP_COMMIT();
            if (++stage == STAGES) stage = 0;
        }

        // ---- epilogue: quad-reduce row sums once; write partials ----
        l0v += __shfl_xor_sync(0xffffffffu, l0v, 1);
        l1v += __shfl_xor_sync(0xffffffffu, l1v, 1);
        l0v += __shfl_xor_sync(0xffffffffu, l0v, 2);
        l1v += __shfl_xor_sync(0xffffffffu, l1v, 2);
        {
            size_t orow0 = (size_t)ri * N_TOK + q0 + w * 16 + r;
            size_t orow8 = orow0 + 8;
#pragma unroll
            for (int nb = 0; nb < 8; nb++) {
                int cc = nb * 8 + 2 * c;
                *(float2*)&g_opart[orow0 * D_OUT + cc] = make_float2(o[nb][0], o[nb][1]);
                *(float2*)&g_opart[orow8 * D_OUT + cc] = make_float2(o[nb][2], o[nb][3]);
            }
            if (c == 0) {
                g_l[orow0] = l0v;
                g_l[orow8] = l1v;
            }
        }

        CP_WAIT0();
        __syncthreads();     // drain before next item reuses smem
    }
}

// ---------------- merge: O = Σo / Σl ----------------------------------------
__global__ __launch_bounds__(256)
void merge_kernel(float* __restrict__ out) {
    int idx = blockIdx.x * blockDim.x + threadIdx.x;
    int row = idx >> 4;
    int c4 = (idx & 15) * 4;

    float L = 0.0f;
#pragma unroll
    for (int s = 0; s < NSPLIT; s++) L += g_l[s * N_TOK + row];

    float4 acc = make_float4(0.f, 0.f, 0.f, 0.f);
#pragma unroll
    for (int s = 0; s < NSPLIT; s++) {
        float4 v = *(const float4*)&g_opart[(size_t)(s * N_TOK + row) * D_OUT + c4];
        acc.x += v.x; acc.y += v.y; acc.z += v.z; acc.w += v.w;
    }
    float inv = 1.0f / L;
    acc.x *= inv; acc.y *= inv; acc.z *= inv; acc.w *= inv;
    *(float4*)&out[(size_t)row * D_OUT + c4] = acc;
}

// ---------------- launch ------------------------------------------------------
extern "C" void kernel_launch(void* const* d_in, const int* in_sizes, int n_in,
                              void* d_out, int out_size) {
    const float* x  = (const float*)d_in[0];
    const float* Wk = (const float*)d_in[1];   // Q side (reference swap)
    const float* Wq = (const float*)d_in[2];   // K side
    const float* Wv = (const float*)d_in[3];
    float* out = (float*)d_out;

    cudaFuncSetAttribute(proj_mma_kernel,
                         cudaFuncAttributeMaxDynamicSharedMemorySize, PSM_TOTAL);
    cudaFuncSetAttribute(attn_kernel,
                         cudaFuncAttributeMaxDynamicSharedMemorySize, SMEM_TOTAL);

    split_x_kernel<<<N_TOK * D_INP / 4 / 256, 256>>>(x);
    split_w_kernel<<<dim3(D_INP * D_OUT / 4 / 256, 3), 256>>>(Wk, Wq, Wv);
    proj_mma_kernel<<<dim3(64, 3), 128, PSM_TOTAL>>>();
    attn_kernel<<<GRID_A, 256, SMEM_TOTAL>>>();
    merge_kernel<<<(N_TOK * 16) / 256, 256>>>(out);
}